// round 1
// baseline (speedup 1.0000x reference)
#include <cuda_runtime.h>
#include <math.h>

#define BB 2
#define TT 2048
#define DD 1024
#define HH 16
#define DH 64
#define MM (BB*TT)      /* 4096 rows of x */
#define AST 68          /* padded smem row stride (floats), 272B => float4-aligned */

// ---------------- scratch (device globals: no allocations allowed) ----------
__device__ float g_q [MM*DD];
__device__ float g_k [MM*DD];
__device__ float g_q2[MM*DD];
__device__ float g_k2[MM*DD];
__device__ float g_v [MM*DD];
__device__ float g_z [MM*DD];

// ---------------------------------------------------------------------------
// C[M,N] = A[M,K] @ W[N,K]^T    (M=4096, N=1024, K=1024)
// 128x128 block tile, K-tile 8, 256 threads, 8x8 per-thread microtile.
// ---------------------------------------------------------------------------
__global__ void __launch_bounds__(256) gemm_atb(const float* __restrict__ A,
                                                const float* __restrict__ W,
                                                float* __restrict__ C) {
    __shared__ float As[8][128];
    __shared__ float Bs[8][128];
    const int m0  = blockIdx.y * 128;
    const int n0  = blockIdx.x * 128;
    const int tid = threadIdx.x;
    const int lrow = tid >> 1;            // 0..127
    const int lseg = (tid & 1) * 4;       // 0 or 4
    const int ty = tid >> 4;              // 0..15
    const int tx = tid & 15;              // 0..15

    const float* Ap = A + (size_t)(m0 + lrow) * DD + lseg;
    const float* Wp = W + (size_t)(n0 + lrow) * DD + lseg;

    float acc[8][8];
#pragma unroll
    for (int i = 0; i < 8; i++)
#pragma unroll
        for (int j = 0; j < 8; j++) acc[i][j] = 0.0f;

    for (int k0 = 0; k0 < DD; k0 += 8) {
        float4 av = *(const float4*)(Ap + k0);
        float4 wv = *(const float4*)(Wp + k0);
        As[lseg+0][lrow] = av.x; As[lseg+1][lrow] = av.y;
        As[lseg+2][lrow] = av.z; As[lseg+3][lrow] = av.w;
        Bs[lseg+0][lrow] = wv.x; Bs[lseg+1][lrow] = wv.y;
        Bs[lseg+2][lrow] = wv.z; Bs[lseg+3][lrow] = wv.w;
        __syncthreads();
#pragma unroll
        for (int kk = 0; kk < 8; kk++) {
            float a[8], b[8];
            *(float4*)(a)     = *(const float4*)(&As[kk][ty*8]);
            *(float4*)(a + 4) = *(const float4*)(&As[kk][ty*8 + 4]);
            *(float4*)(b)     = *(const float4*)(&Bs[kk][tx*8]);
            *(float4*)(b + 4) = *(const float4*)(&Bs[kk][tx*8 + 4]);
#pragma unroll
            for (int i = 0; i < 8; i++)
#pragma unroll
                for (int j = 0; j < 8; j++)
                    acc[i][j] = fmaf(a[i], b[j], acc[i][j]);
        }
        __syncthreads();
    }
#pragma unroll
    for (int i = 0; i < 8; i++) {
        float* Cp = C + (size_t)(m0 + ty*8 + i) * 1024 + n0 + tx*8;
#pragma unroll
        for (int j = 0; j < 8; j += 4) {
            float4 o = make_float4(acc[i][j], acc[i][j+1], acc[i][j+2], acc[i][j+3]);
            *(float4*)(Cp + j) = o;
        }
    }
}

// ---------------------------------------------------------------------------
// In-place RoPE on q, k, q2, k2 ([B,T,H,Dh] layout, pair (i, i+32))
// ---------------------------------------------------------------------------
__global__ void rope_all(float* __restrict__ q, float* __restrict__ k,
                         float* __restrict__ q2, float* __restrict__ k2) {
    const int idx = blockIdx.x * blockDim.x + threadIdx.x;   // < 2^21
    const int i = idx & 31;
    const int h = (idx >> 5) & (HH - 1);
    const int t = (idx >> 9) & (TT - 1);
    const int b = idx >> 20;

    const float inv_freq = powf(10000.0f, -(float)i * (1.0f / 32.0f));
    float c, s;
    sincosf((float)t * inv_freq, &s, &c);  // note: sincosf(x, &sin, &cos)

    const size_t base = ((size_t)(b * TT + t)) * DD + h * DH + i;

    float* ptrs[4] = {q, k, q2, k2};
#pragma unroll
    for (int a = 0; a < 4; a++) {
        float* p = ptrs[a];
        float x1 = p[base];
        float x2 = p[base + 32];
        p[base]      = fmaf(x1, c, x2 * s);
        p[base + 32] = fmaf(-x1, s, x2 * c);
    }
}

// ---------------------------------------------------------------------------
// Causal bilinear attention, per (b,h): 64x64 q-tile per CTA.
//   s1 = Q K^T, s2 = Q2 K2^T, P = mask(s1*s2)/Dh^2, Z += P V
// Smem: Qs,Q2s,Ks,K2s transposed [d][row]; Vs natural [row][d]; Ps reuses Ks.
// ---------------------------------------------------------------------------
__global__ void __launch_bounds__(256) attn_kernel(const float* __restrict__ q,
        const float* __restrict__ k,  const float* __restrict__ q2,
        const float* __restrict__ k2, const float* __restrict__ v,
        float* __restrict__ z) {
    extern __shared__ float sm[];
    float* Qs  = sm;                 // [64][AST] transposed
    float* Q2s = Qs  + DH * AST;
    float* Ks  = Q2s + DH * AST;     // [64][AST] transposed; reused as Ps[j][i]
    float* K2s = Ks  + DH * AST;
    float* Vs  = K2s + DH * AST;     // [64][AST] natural

    const int qi = (int)gridDim.x - 1 - (int)blockIdx.x;  // heavy tiles first
    const int bh = blockIdx.y;
    const int b  = bh >> 4;
    const int h  = bh & 15;
    const int tid = threadIdx.x;
    const int tx = tid & 15;
    const int ty = tid >> 4;
    const int c4 = (tid & 15) * 4;   // d offset for loads
    const int r0 = tid >> 4;         // row base for loads

    // Load Q, Q2 tile (transposed into smem)
    const size_t qoff = ((size_t)(b * TT + qi * 64)) * DD + h * DH;
#pragma unroll
    for (int rr = 0; rr < 4; rr++) {
        const int i = r0 + rr * 16;
        float4 a  = *(const float4*)(q  + qoff + (size_t)i * DD + c4);
        float4 a2 = *(const float4*)(q2 + qoff + (size_t)i * DD + c4);
        Qs [(c4+0)*AST + i] = a.x;  Qs [(c4+1)*AST + i] = a.y;
        Qs [(c4+2)*AST + i] = a.z;  Qs [(c4+3)*AST + i] = a.w;
        Q2s[(c4+0)*AST + i] = a2.x; Q2s[(c4+1)*AST + i] = a2.y;
        Q2s[(c4+2)*AST + i] = a2.z; Q2s[(c4+3)*AST + i] = a2.w;
    }

    float zacc[4][4];
#pragma unroll
    for (int i = 0; i < 4; i++)
#pragma unroll
        for (int j = 0; j < 4; j++) zacc[i][j] = 0.0f;

    const float invd2 = 1.0f / ((float)DH * (float)DH);

    for (int kj = 0; kj <= qi; kj++) {
        __syncthreads();  // prior PV reads done (also fences initial Q stores)

        const size_t koff = ((size_t)(b * TT + kj * 64)) * DD + h * DH;
#pragma unroll
        for (int rr = 0; rr < 4; rr++) {
            const int i = r0 + rr * 16;
            float4 ka  = *(const float4*)(k  + koff + (size_t)i * DD + c4);
            float4 k2a = *(const float4*)(k2 + koff + (size_t)i * DD + c4);
            float4 va  = *(const float4*)(v  + koff + (size_t)i * DD + c4);
            Ks [(c4+0)*AST + i] = ka.x;  Ks [(c4+1)*AST + i] = ka.y;
            Ks [(c4+2)*AST + i] = ka.z;  Ks [(c4+3)*AST + i] = ka.w;
            K2s[(c4+0)*AST + i] = k2a.x; K2s[(c4+1)*AST + i] = k2a.y;
            K2s[(c4+2)*AST + i] = k2a.z; K2s[(c4+3)*AST + i] = k2a.w;
            *(float4*)(&Vs[i * AST + c4]) = va;
        }
        __syncthreads();

        // S1 = Q K^T, S2 = Q2 K2^T (4x4 per thread)
        float s1[4][4], s2[4][4];
#pragma unroll
        for (int i = 0; i < 4; i++)
#pragma unroll
            for (int j = 0; j < 4; j++) { s1[i][j] = 0.0f; s2[i][j] = 0.0f; }

#pragma unroll 8
        for (int d = 0; d < DH; d++) {
            float qa[4], q2a[4], ka[4], k2a[4];
            *(float4*)qa  = *(const float4*)(&Qs [d * AST + ty * 4]);
            *(float4*)q2a = *(const float4*)(&Q2s[d * AST + ty * 4]);
            *(float4*)ka  = *(const float4*)(&Ks [d * AST + tx * 4]);
            *(float4*)k2a = *(const float4*)(&K2s[d * AST + tx * 4]);
#pragma unroll
            for (int i = 0; i < 4; i++)
#pragma unroll
                for (int j = 0; j < 4; j++) {
                    s1[i][j] = fmaf(qa[i],  ka[j],  s1[i][j]);
                    s2[i][j] = fmaf(q2a[i], k2a[j], s2[i][j]);
                }
        }
        __syncthreads();  // all reads of Ks done; reuse region as Ps

        float* Ps = Ks;   // Ps[j][i] (k index major) for conflict-free PV reads
        const bool diag = (kj == qi);
#pragma unroll
        for (int j = 0; j < 4; j++)
#pragma unroll
            for (int i = 0; i < 4; i++) {
                float p = s1[i][j] * s2[i][j] * invd2;
                if (diag && (tx * 4 + j > ty * 4 + i)) p = 0.0f;
                Ps[(tx * 4 + j) * AST + ty * 4 + i] = p;
            }
        __syncthreads();

        // Z += P V
#pragma unroll 4
        for (int j = 0; j < 64; j++) {
            float pa[4], va[4];
            *(float4*)pa = *(const float4*)(&Ps[j * AST + ty * 4]);
            *(float4*)va = *(const float4*)(&Vs[j * AST + tx * 4]);
#pragma unroll
            for (int i = 0; i < 4; i++)
#pragma unroll
                for (int dd = 0; dd < 4; dd++)
                    zacc[i][dd] = fmaf(pa[i], va[dd], zacc[i][dd]);
        }
    }

    // write Z tile: [B,T,H,Dh] layout
    const size_t zoff = ((size_t)(b * TT + qi * 64)) * DD + h * DH;
#pragma unroll
    for (int i = 0; i < 4; i++) {
        float4 o = make_float4(zacc[i][0], zacc[i][1], zacc[i][2], zacc[i][3]);
        *(float4*)(z + zoff + (size_t)(ty * 4 + i) * DD + tx * 4) = o;
    }
}

// ---------------------------------------------------------------------------
extern "C" void kernel_launch(void* const* d_in, const int* in_sizes, int n_in,
                              void* d_out, int out_size) {
    const float* x     = (const float*)d_in[0];
    const float* Wq    = (const float*)d_in[1];
    const float* Wk    = (const float*)d_in[2];
    const float* Wq2   = (const float*)d_in[3];
    const float* Wk2   = (const float*)d_in[4];
    const float* Wv    = (const float*)d_in[5];
    const float* Wproj = (const float*)d_in[6];
    float* out = (float*)d_out;

    float *q, *k, *q2, *k2, *v, *z;
    cudaGetSymbolAddress((void**)&q,  g_q);
    cudaGetSymbolAddress((void**)&k,  g_k);
    cudaGetSymbolAddress((void**)&q2, g_q2);
    cudaGetSymbolAddress((void**)&k2, g_k2);
    cudaGetSymbolAddress((void**)&v,  g_v);
    cudaGetSymbolAddress((void**)&z,  g_z);

    const dim3 ggrid(DD / 128, MM / 128);   // (8, 32)

    gemm_atb<<<ggrid, 256>>>(x, Wq,  q);
    gemm_atb<<<ggrid, 256>>>(x, Wk,  k);
    gemm_atb<<<ggrid, 256>>>(x, Wq2, q2);
    gemm_atb<<<ggrid, 256>>>(x, Wk2, k2);
    gemm_atb<<<ggrid, 256>>>(x, Wv,  v);

    rope_all<<<(BB * TT * HH * 32) / 256, 256>>>(q, k, q2, k2);

    const int attn_smem = 5 * DH * AST * (int)sizeof(float);  // 87040 B
    cudaFuncSetAttribute(attn_kernel,
                         cudaFuncAttributeMaxDynamicSharedMemorySize, attn_smem);
    attn_kernel<<<dim3(TT / 64, BB * HH), 256, attn_smem>>>(q, k, q2, k2, v, z);

    gemm_atb<<<ggrid, 256>>>(z, Wproj, out);
}

// round 2
// speedup vs baseline: 1.5013x; 1.5013x over previous
#include <cuda_runtime.h>
#include <cuda_bf16.h>
#include <math.h>
#include <stdint.h>

#define BB 2
#define TT 2048
#define DD 1024
#define HH 16
#define DH 64
#define MM (BB*TT)      /* 4096 rows of x */
#define AST 68          /* attn smem row stride (floats) */

#define SST 40          /* gemm smem row stride in bf16 (80B, ldmatrix conflict-free) */
#define TILEE (128*SST) /* 5120 bf16 per tile */
#define BUFE  (4*TILEE) /* Ahi,Alo,Bhi,Blo per buffer */

// ---------------- scratch (device globals: no allocations allowed) ----------
__device__ float g_q [MM*DD];
__device__ float g_k [MM*DD];
__device__ float g_q2[MM*DD];
__device__ float g_k2[MM*DD];
__device__ float g_v [MM*DD];
__device__ float g_z [MM*DD];

// ---------------------------------------------------------------------------
// helpers
// ---------------------------------------------------------------------------
__device__ __forceinline__ uint32_t saddr(const void* p) {
    return (uint32_t)__cvta_generic_to_shared(p);
}

__device__ __forceinline__ void ldmat_x4(uint32_t (&r)[4], uint32_t a) {
    asm volatile("ldmatrix.sync.aligned.m8n8.x4.shared.b16 {%0,%1,%2,%3}, [%4];"
                 : "=r"(r[0]), "=r"(r[1]), "=r"(r[2]), "=r"(r[3]) : "r"(a));
}

__device__ __forceinline__ void mma16816(float (&d)[4], const uint32_t (&a)[4],
                                         uint32_t b0, uint32_t b1) {
    asm volatile(
        "mma.sync.aligned.m16n8k16.row.col.f32.bf16.bf16.f32 "
        "{%0,%1,%2,%3}, {%4,%5,%6,%7}, {%8,%9}, {%0,%1,%2,%3};"
        : "+f"(d[0]), "+f"(d[1]), "+f"(d[2]), "+f"(d[3])
        : "r"(a[0]), "r"(a[1]), "r"(a[2]), "r"(a[3]), "r"(b0), "r"(b1));
}

// convert one float4 -> bf16 hi/lo pairs, store 8B each into smem tile
__device__ __forceinline__ void cvst(__nv_bfloat16* hi, __nv_bfloat16* lo,
                                     int row, int kc, float4 v) {
    float f[4] = {v.x, v.y, v.z, v.w};
    unsigned short h[4], l[4];
#pragma unroll
    for (int i = 0; i < 4; i++) {
        __nv_bfloat16 hb = __float2bfloat16_rn(f[i]);
        float res = f[i] - __bfloat162float(hb);
        __nv_bfloat16 lb = __float2bfloat16_rn(res);
        h[i] = __bfloat16_as_ushort(hb);
        l[i] = __bfloat16_as_ushort(lb);
    }
    const int off = row * SST + kc;
    *(uint2*)(hi + off) = make_uint2((uint32_t)h[1] << 16 | h[0],
                                     (uint32_t)h[3] << 16 | h[2]);
    *(uint2*)(lo + off) = make_uint2((uint32_t)l[1] << 16 | l[0],
                                     (uint32_t)l[3] << 16 | l[2]);
}

// ---------------------------------------------------------------------------
// C[M,N] = A[M,K] @ W[N,K]^T via 3xBF16 mma.sync (hi*hi + hi*lo + lo*hi)
// 128x128 CTA tile, 8 warps (64x32 each), k-stage 32, double-buffered smem.
// ---------------------------------------------------------------------------
__global__ void __launch_bounds__(256, 1) gemm_mma(const float* __restrict__ A,
                                                   const float* __restrict__ W,
                                                   float* __restrict__ C) {
    extern __shared__ __nv_bfloat16 sb[];
    const int tid  = threadIdx.x;
    const int wid  = tid >> 5;
    const int lane = tid & 31;
    const int m0 = blockIdx.y * 128;
    const int n0 = blockIdx.x * 128;
    const int wm = wid & 1;         // 0..1 -> 64-row slab
    const int wn = wid >> 1;        // 0..3 -> 32-col slab

    // global load mapping: 2 threads per 128-row, 16 k's each
    const int lrow = tid >> 1;
    const int lk   = (tid & 1) * 16;
    const float* Ap = A + (size_t)(m0 + lrow) * DD + lk;
    const float* Wp = W + (size_t)(n0 + lrow) * DD + lk;

    __nv_bfloat16* buf0 = sb;
    __nv_bfloat16* buf1 = sb + BUFE;

    float acc[4][4][4];
#pragma unroll
    for (int i = 0; i < 4; i++)
#pragma unroll
        for (int j = 0; j < 4; j++)
#pragma unroll
            for (int c = 0; c < 4; c++) acc[i][j][c] = 0.0f;

    float4 pa[4], pb[4];
#pragma unroll
    for (int j = 0; j < 4; j++) {
        pa[j] = *(const float4*)(Ap + j * 4);
        pb[j] = *(const float4*)(Wp + j * 4);
    }
    {
        __nv_bfloat16* Ahi = buf0;
        __nv_bfloat16* Alo = buf0 + TILEE;
        __nv_bfloat16* Bhi = buf0 + 2 * TILEE;
        __nv_bfloat16* Blo = buf0 + 3 * TILEE;
#pragma unroll
        for (int j = 0; j < 4; j++) {
            cvst(Ahi, Alo, lrow, lk + j * 4, pa[j]);
            cvst(Bhi, Blo, lrow, lk + j * 4, pb[j]);
        }
    }
    __syncthreads();

    for (int s = 0; s < 32; s++) {
        const __nv_bfloat16* cur = (s & 1) ? buf1 : buf0;
        __nv_bfloat16* nxt = (s & 1) ? buf0 : buf1;

        if (s < 31) {
            const int kb = (s + 1) * 32;
#pragma unroll
            for (int j = 0; j < 4; j++) {
                pa[j] = *(const float4*)(Ap + kb + j * 4);
                pb[j] = *(const float4*)(Wp + kb + j * 4);
            }
        }

        const __nv_bfloat16* Ahi = cur;
        const __nv_bfloat16* Alo = cur + TILEE;
        const __nv_bfloat16* Bhi = cur + 2 * TILEE;
        const __nv_bfloat16* Blo = cur + 3 * TILEE;

#pragma unroll
        for (int kk = 0; kk < 2; kk++) {
            uint32_t ahi[4][4], alo[4][4], bhi[2][4], blo[2][4];
            const int ar = wm * 64 + (lane & 15);
            const int ak = kk * 16 + (lane >> 4) * 8;
#pragma unroll
            for (int mi = 0; mi < 4; mi++) {
                ldmat_x4(ahi[mi], saddr(Ahi + (ar + mi * 16) * SST + ak));
                ldmat_x4(alo[mi], saddr(Alo + (ar + mi * 16) * SST + ak));
            }
            const int br = wn * 32 + ((lane >> 4) & 1) * 8 + (lane & 7);
            const int bk = kk * 16 + ((lane >> 3) & 1) * 8;
#pragma unroll
            for (int p = 0; p < 2; p++) {
                ldmat_x4(bhi[p], saddr(Bhi + (br + p * 16) * SST + bk));
                ldmat_x4(blo[p], saddr(Blo + (br + p * 16) * SST + bk));
            }
#pragma unroll
            for (int mi = 0; mi < 4; mi++)
#pragma unroll
                for (int ni = 0; ni < 4; ni++) {
                    const uint32_t* bh = &bhi[ni >> 1][(ni & 1) * 2];
                    const uint32_t* bl = &blo[ni >> 1][(ni & 1) * 2];
                    mma16816(acc[mi][ni], ahi[mi], bh[0], bh[1]);
                    mma16816(acc[mi][ni], ahi[mi], bl[0], bl[1]);
                    mma16816(acc[mi][ni], alo[mi], bh[0], bh[1]);
                }
        }

        if (s < 31) {
            __nv_bfloat16* Ahw = nxt;
            __nv_bfloat16* Alw = nxt + TILEE;
            __nv_bfloat16* Bhw = nxt + 2 * TILEE;
            __nv_bfloat16* Blw = nxt + 3 * TILEE;
#pragma unroll
            for (int j = 0; j < 4; j++) {
                cvst(Ahw, Alw, lrow, lk + j * 4, pa[j]);
                cvst(Bhw, Blw, lrow, lk + j * 4, pb[j]);
            }
        }
        __syncthreads();
    }

    // epilogue: frag (mi,ni): rows r0, r0+8; cols c0, c0+1
#pragma unroll
    for (int mi = 0; mi < 4; mi++)
#pragma unroll
        for (int ni = 0; ni < 4; ni++) {
            const int r0 = m0 + wm * 64 + mi * 16 + (lane >> 2);
            const int c0 = n0 + wn * 32 + ni * 8 + (lane & 3) * 2;
            *(float2*)(C + (size_t)r0 * 1024 + c0) =
                make_float2(acc[mi][ni][0], acc[mi][ni][1]);
            *(float2*)(C + (size_t)(r0 + 8) * 1024 + c0) =
                make_float2(acc[mi][ni][2], acc[mi][ni][3]);
        }
}

// ---------------------------------------------------------------------------
// In-place RoPE on q, k, q2, k2 ([B,T,H,Dh] layout, pair (i, i+32))
// ---------------------------------------------------------------------------
__global__ void rope_all(float* __restrict__ q, float* __restrict__ k,
                         float* __restrict__ q2, float* __restrict__ k2) {
    const int idx = blockIdx.x * blockDim.x + threadIdx.x;
    const int i = idx & 31;
    const int h = (idx >> 5) & (HH - 1);
    const int t = (idx >> 9) & (TT - 1);
    const int b = idx >> 20;

    const float inv_freq = powf(10000.0f, -(float)i * (1.0f / 32.0f));
    float c, s;
    sincosf((float)t * inv_freq, &s, &c);

    const size_t base = ((size_t)(b * TT + t)) * DD + h * DH + i;

    float* ptrs[4] = {q, k, q2, k2};
#pragma unroll
    for (int a = 0; a < 4; a++) {
        float* p = ptrs[a];
        float x1 = p[base];
        float x2 = p[base + 32];
        p[base]      = fmaf(x1, c, x2 * s);
        p[base + 32] = fmaf(-x1, s, x2 * c);
    }
}

// ---------------------------------------------------------------------------
// Causal bilinear attention, per (b,h): 64x64 q-tile per CTA (fp32 SIMT).
// ---------------------------------------------------------------------------
__global__ void __launch_bounds__(256) attn_kernel(const float* __restrict__ q,
        const float* __restrict__ k,  const float* __restrict__ q2,
        const float* __restrict__ k2, const float* __restrict__ v,
        float* __restrict__ z) {
    extern __shared__ float sm[];
    float* Qs  = sm;
    float* Q2s = Qs  + DH * AST;
    float* Ks  = Q2s + DH * AST;
    float* K2s = Ks  + DH * AST;
    float* Vs  = K2s + DH * AST;

    const int qi = (int)gridDim.x - 1 - (int)blockIdx.x;
    const int bh = blockIdx.y;
    const int b  = bh >> 4;
    const int h  = bh & 15;
    const int tid = threadIdx.x;
    const int tx = tid & 15;
    const int ty = tid >> 4;
    const int c4 = (tid & 15) * 4;
    const int r0 = tid >> 4;

    const size_t qoff = ((size_t)(b * TT + qi * 64)) * DD + h * DH;
#pragma unroll
    for (int rr = 0; rr < 4; rr++) {
        const int i = r0 + rr * 16;
        float4 a  = *(const float4*)(q  + qoff + (size_t)i * DD + c4);
        float4 a2 = *(const float4*)(q2 + qoff + (size_t)i * DD + c4);
        Qs [(c4+0)*AST + i] = a.x;  Qs [(c4+1)*AST + i] = a.y;
        Qs [(c4+2)*AST + i] = a.z;  Qs [(c4+3)*AST + i] = a.w;
        Q2s[(c4+0)*AST + i] = a2.x; Q2s[(c4+1)*AST + i] = a2.y;
        Q2s[(c4+2)*AST + i] = a2.z; Q2s[(c4+3)*AST + i] = a2.w;
    }

    float zacc[4][4];
#pragma unroll
    for (int i = 0; i < 4; i++)
#pragma unroll
        for (int j = 0; j < 4; j++) zacc[i][j] = 0.0f;

    const float invd2 = 1.0f / ((float)DH * (float)DH);

    for (int kj = 0; kj <= qi; kj++) {
        __syncthreads();

        const size_t koff = ((size_t)(b * TT + kj * 64)) * DD + h * DH;
#pragma unroll
        for (int rr = 0; rr < 4; rr++) {
            const int i = r0 + rr * 16;
            float4 ka  = *(const float4*)(k  + koff + (size_t)i * DD + c4);
            float4 k2a = *(const float4*)(k2 + koff + (size_t)i * DD + c4);
            float4 va  = *(const float4*)(v  + koff + (size_t)i * DD + c4);
            Ks [(c4+0)*AST + i] = ka.x;  Ks [(c4+1)*AST + i] = ka.y;
            Ks [(c4+2)*AST + i] = ka.z;  Ks [(c4+3)*AST + i] = ka.w;
            K2s[(c4+0)*AST + i] = k2a.x; K2s[(c4+1)*AST + i] = k2a.y;
            K2s[(c4+2)*AST + i] = k2a.z; K2s[(c4+3)*AST + i] = k2a.w;
            *(float4*)(&Vs[i * AST + c4]) = va;
        }
        __syncthreads();

        float s1[4][4], s2[4][4];
#pragma unroll
        for (int i = 0; i < 4; i++)
#pragma unroll
            for (int j = 0; j < 4; j++) { s1[i][j] = 0.0f; s2[i][j] = 0.0f; }

#pragma unroll 8
        for (int d = 0; d < DH; d++) {
            float qa[4], q2a[4], ka[4], k2a[4];
            *(float4*)qa  = *(const float4*)(&Qs [d * AST + ty * 4]);
            *(float4*)q2a = *(const float4*)(&Q2s[d * AST + ty * 4]);
            *(float4*)ka  = *(const float4*)(&Ks [d * AST + tx * 4]);
            *(float4*)k2a = *(const float4*)(&K2s[d * AST + tx * 4]);
#pragma unroll
            for (int i = 0; i < 4; i++)
#pragma unroll
                for (int j = 0; j < 4; j++) {
                    s1[i][j] = fmaf(qa[i],  ka[j],  s1[i][j]);
                    s2[i][j] = fmaf(q2a[i], k2a[j], s2[i][j]);
                }
        }
        __syncthreads();

        float* Ps = Ks;
        const bool diag = (kj == qi);
#pragma unroll
        for (int j = 0; j < 4; j++)
#pragma unroll
            for (int i = 0; i < 4; i++) {
                float p = s1[i][j] * s2[i][j] * invd2;
                if (diag && (tx * 4 + j > ty * 4 + i)) p = 0.0f;
                Ps[(tx * 4 + j) * AST + ty * 4 + i] = p;
            }
        __syncthreads();

#pragma unroll 4
        for (int j = 0; j < 64; j++) {
            float pa[4], va[4];
            *(float4*)pa = *(const float4*)(&Ps[j * AST + ty * 4]);
            *(float4*)va = *(const float4*)(&Vs[j * AST + tx * 4]);
#pragma unroll
            for (int i = 0; i < 4; i++)
#pragma unroll
                for (int dd = 0; dd < 4; dd++)
                    zacc[i][dd] = fmaf(pa[i], va[dd], zacc[i][dd]);
        }
    }

    const size_t zoff = ((size_t)(b * TT + qi * 64)) * DD + h * DH;
#pragma unroll
    for (int i = 0; i < 4; i++) {
        float4 o = make_float4(zacc[i][0], zacc[i][1], zacc[i][2], zacc[i][3]);
        *(float4*)(z + zoff + (size_t)(ty * 4 + i) * DD + tx * 4) = o;
    }
}

// ---------------------------------------------------------------------------
extern "C" void kernel_launch(void* const* d_in, const int* in_sizes, int n_in,
                              void* d_out, int out_size) {
    const float* x     = (const float*)d_in[0];
    const float* Wq    = (const float*)d_in[1];
    const float* Wk    = (const float*)d_in[2];
    const float* Wq2   = (const float*)d_in[3];
    const float* Wk2   = (const float*)d_in[4];
    const float* Wv    = (const float*)d_in[5];
    const float* Wproj = (const float*)d_in[6];
    float* out = (float*)d_out;

    float *q, *k, *q2, *k2, *v, *z;
    cudaGetSymbolAddress((void**)&q,  g_q);
    cudaGetSymbolAddress((void**)&k,  g_k);
    cudaGetSymbolAddress((void**)&q2, g_q2);
    cudaGetSymbolAddress((void**)&k2, g_k2);
    cudaGetSymbolAddress((void**)&v,  g_v);
    cudaGetSymbolAddress((void**)&z,  g_z);

    const dim3 ggrid(DD / 128, MM / 128);   // (8, 32)
    const int gemm_smem = 2 * BUFE * (int)sizeof(__nv_bfloat16);  // 81920 B
    cudaFuncSetAttribute(gemm_mma,
                         cudaFuncAttributeMaxDynamicSharedMemorySize, gemm_smem);

    gemm_mma<<<ggrid, 256, gemm_smem>>>(x, Wq,  q);
    gemm_mma<<<ggrid, 256, gemm_smem>>>(x, Wk,  k);
    gemm_mma<<<ggrid, 256, gemm_smem>>>(x, Wq2, q2);
    gemm_mma<<<ggrid, 256, gemm_smem>>>(x, Wk2, k2);
    gemm_mma<<<ggrid, 256, gemm_smem>>>(x, Wv,  v);

    rope_all<<<(BB * TT * HH * 32) / 256, 256>>>(q, k, q2, k2);

    const int attn_smem = 5 * DH * AST * (int)sizeof(float);  // 87040 B
    cudaFuncSetAttribute(attn_kernel,
                         cudaFuncAttributeMaxDynamicSharedMemorySize, attn_smem);
    attn_kernel<<<dim3(TT / 64, BB * HH), 256, attn_smem>>>(q, k, q2, k2, v, z);

    gemm_mma<<<ggrid, 256, gemm_smem>>>(z, Wproj, out);
}

// round 3
// speedup vs baseline: 2.3722x; 1.5801x over previous
#include <cuda_runtime.h>
#include <cuda_bf16.h>
#include <math.h>
#include <stdint.h>

#define BB 2
#define TT 2048
#define DD 1024
#define HH 16
#define DH 64
#define MM (BB*TT)

#define SST 40           /* gemm smem row stride (bf16) */
#define TILEE (128*SST)
#define BUFE  (4*TILEE)

#define KST 72           /* attn smem row stride (bf16): 144B, odd*16B => conflict-free */
#define ATILE (64*KST)   /* 4608 bf16 per 64x64 tile */
#define STAGE (6*ATILE)  /* khi,klo,k2hi,k2lo,vthi,vtlo */

// ---------------- scratch (device globals) ----------------------------------
__device__ float g_q [MM*DD];
__device__ float g_k [MM*DD];
__device__ float g_q2[MM*DD];
__device__ float g_k2[MM*DD];
__device__ float g_v [MM*DD];
__device__ float g_z [MM*DD];
__device__ __nv_bfloat16 g_qh [MM*DD], g_ql [MM*DD];
__device__ __nv_bfloat16 g_q2h[MM*DD], g_q2l[MM*DD];
__device__ __nv_bfloat16 g_kh [MM*DD], g_kl [MM*DD];
__device__ __nv_bfloat16 g_k2h[MM*DD], g_k2l[MM*DD];
__device__ __nv_bfloat16 g_vh [MM*DD], g_vl [MM*DD];

// ---------------------------------------------------------------------------
__device__ __forceinline__ uint32_t saddr(const void* p) {
    return (uint32_t)__cvta_generic_to_shared(p);
}
__device__ __forceinline__ void ldmat_x4(uint32_t (&r)[4], uint32_t a) {
    asm volatile("ldmatrix.sync.aligned.m8n8.x4.shared.b16 {%0,%1,%2,%3}, [%4];"
                 : "=r"(r[0]), "=r"(r[1]), "=r"(r[2]), "=r"(r[3]) : "r"(a));
}
__device__ __forceinline__ void mma16816(float (&d)[4], const uint32_t (&a)[4],
                                         uint32_t b0, uint32_t b1) {
    asm volatile(
        "mma.sync.aligned.m16n8k16.row.col.f32.bf16.bf16.f32 "
        "{%0,%1,%2,%3}, {%4,%5,%6,%7}, {%8,%9}, {%0,%1,%2,%3};"
        : "+f"(d[0]), "+f"(d[1]), "+f"(d[2]), "+f"(d[3])
        : "r"(a[0]), "r"(a[1]), "r"(a[2]), "r"(a[3]), "r"(b0), "r"(b1));
}
__device__ __forceinline__ void cpa16(void* dst, const void* src) {
    asm volatile("cp.async.cg.shared.global [%0], [%1], 16;"
                 :: "r"(saddr(dst)), "l"(src));
}
__device__ __forceinline__ void cpa_commit() { asm volatile("cp.async.commit_group;"); }
__device__ __forceinline__ void cpa_wait0()  { asm volatile("cp.async.wait_group 0;"); }

__device__ __forceinline__ void fsplit(float x, unsigned short& h, unsigned short& l) {
    __nv_bfloat16 hb = __float2bfloat16_rn(x);
    __nv_bfloat16 lb = __float2bfloat16_rn(x - __bfloat162float(hb));
    h = __bfloat16_as_ushort(hb);
    l = __bfloat16_as_ushort(lb);
}

// ---------------------------------------------------------------------------
// GEMM (unchanged from round 2): C[M,N] = A @ W^T, 3xBF16 mma
// ---------------------------------------------------------------------------
__device__ __forceinline__ void cvst(__nv_bfloat16* hi, __nv_bfloat16* lo,
                                     int row, int kc, float4 v) {
    float f[4] = {v.x, v.y, v.z, v.w};
    unsigned short h[4], l[4];
#pragma unroll
    for (int i = 0; i < 4; i++) fsplit(f[i], h[i], l[i]);
    const int off = row * SST + kc;
    *(uint2*)(hi + off) = make_uint2((uint32_t)h[1] << 16 | h[0],
                                     (uint32_t)h[3] << 16 | h[2]);
    *(uint2*)(lo + off) = make_uint2((uint32_t)l[1] << 16 | l[0],
                                     (uint32_t)l[3] << 16 | l[2]);
}

__global__ void __launch_bounds__(256, 1) gemm_mma(const float* __restrict__ A,
                                                   const float* __restrict__ W,
                                                   float* __restrict__ C) {
    extern __shared__ __nv_bfloat16 sb[];
    const int tid  = threadIdx.x;
    const int wid  = tid >> 5;
    const int lane = tid & 31;
    const int m0 = blockIdx.y * 128;
    const int n0 = blockIdx.x * 128;
    const int wm = wid & 1;
    const int wn = wid >> 1;

    const int lrow = tid >> 1;
    const int lk   = (tid & 1) * 16;
    const float* Ap = A + (size_t)(m0 + lrow) * DD + lk;
    const float* Wp = W + (size_t)(n0 + lrow) * DD + lk;

    __nv_bfloat16* buf0 = sb;
    __nv_bfloat16* buf1 = sb + BUFE;

    float acc[4][4][4];
#pragma unroll
    for (int i = 0; i < 4; i++)
#pragma unroll
        for (int j = 0; j < 4; j++)
#pragma unroll
            for (int c = 0; c < 4; c++) acc[i][j][c] = 0.0f;

    float4 pa[4], pb[4];
#pragma unroll
    for (int j = 0; j < 4; j++) {
        pa[j] = *(const float4*)(Ap + j * 4);
        pb[j] = *(const float4*)(Wp + j * 4);
    }
    {
        __nv_bfloat16* Ahi = buf0;
        __nv_bfloat16* Alo = buf0 + TILEE;
        __nv_bfloat16* Bhi = buf0 + 2 * TILEE;
        __nv_bfloat16* Blo = buf0 + 3 * TILEE;
#pragma unroll
        for (int j = 0; j < 4; j++) {
            cvst(Ahi, Alo, lrow, lk + j * 4, pa[j]);
            cvst(Bhi, Blo, lrow, lk + j * 4, pb[j]);
        }
    }
    __syncthreads();

    for (int s = 0; s < 32; s++) {
        const __nv_bfloat16* cur = (s & 1) ? buf1 : buf0;
        __nv_bfloat16* nxt = (s & 1) ? buf0 : buf1;

        if (s < 31) {
            const int kb = (s + 1) * 32;
#pragma unroll
            for (int j = 0; j < 4; j++) {
                pa[j] = *(const float4*)(Ap + kb + j * 4);
                pb[j] = *(const float4*)(Wp + kb + j * 4);
            }
        }

        const __nv_bfloat16* Ahi = cur;
        const __nv_bfloat16* Alo = cur + TILEE;
        const __nv_bfloat16* Bhi = cur + 2 * TILEE;
        const __nv_bfloat16* Blo = cur + 3 * TILEE;

#pragma unroll
        for (int kk = 0; kk < 2; kk++) {
            uint32_t ahi[4][4], alo[4][4], bhi[2][4], blo[2][4];
            const int ar = wm * 64 + (lane & 15);
            const int ak = kk * 16 + (lane >> 4) * 8;
#pragma unroll
            for (int mi = 0; mi < 4; mi++) {
                ldmat_x4(ahi[mi], saddr(Ahi + (ar + mi * 16) * SST + ak));
                ldmat_x4(alo[mi], saddr(Alo + (ar + mi * 16) * SST + ak));
            }
            const int br = wn * 32 + ((lane >> 4) & 1) * 8 + (lane & 7);
            const int bk = kk * 16 + ((lane >> 3) & 1) * 8;
#pragma unroll
            for (int p = 0; p < 2; p++) {
                ldmat_x4(bhi[p], saddr(Bhi + (br + p * 16) * SST + bk));
                ldmat_x4(blo[p], saddr(Blo + (br + p * 16) * SST + bk));
            }
#pragma unroll
            for (int mi = 0; mi < 4; mi++)
#pragma unroll
                for (int ni = 0; ni < 4; ni++) {
                    const uint32_t* bh = &bhi[ni >> 1][(ni & 1) * 2];
                    const uint32_t* bl = &blo[ni >> 1][(ni & 1) * 2];
                    mma16816(acc[mi][ni], ahi[mi], bh[0], bh[1]);
                    mma16816(acc[mi][ni], ahi[mi], bl[0], bl[1]);
                    mma16816(acc[mi][ni], alo[mi], bh[0], bh[1]);
                }
        }

        if (s < 31) {
            __nv_bfloat16* Ahw = nxt;
            __nv_bfloat16* Alw = nxt + TILEE;
            __nv_bfloat16* Bhw = nxt + 2 * TILEE;
            __nv_bfloat16* Blw = nxt + 3 * TILEE;
#pragma unroll
            for (int j = 0; j < 4; j++) {
                cvst(Ahw, Alw, lrow, lk + j * 4, pa[j]);
                cvst(Bhw, Blw, lrow, lk + j * 4, pb[j]);
            }
        }
        __syncthreads();
    }

#pragma unroll
    for (int mi = 0; mi < 4; mi++)
#pragma unroll
        for (int ni = 0; ni < 4; ni++) {
            const int r0 = m0 + wm * 64 + mi * 16 + (lane >> 2);
            const int c0 = n0 + wn * 32 + ni * 8 + (lane & 3) * 2;
            *(float2*)(C + (size_t)r0 * 1024 + c0) =
                make_float2(acc[mi][ni][0], acc[mi][ni][1]);
            *(float2*)(C + (size_t)(r0 + 8) * 1024 + c0) =
                make_float2(acc[mi][ni][2], acc[mi][ni][3]);
        }
}

// ---------------------------------------------------------------------------
// RoPE + split to bf16 hi/lo (q,k,q2,k2 rotated; v plain split)
// ---------------------------------------------------------------------------
__global__ void rope_split(const float* __restrict__ q,  const float* __restrict__ k,
                           const float* __restrict__ q2, const float* __restrict__ k2,
                           const float* __restrict__ v,
                           __nv_bfloat16* __restrict__ qh,  __nv_bfloat16* __restrict__ ql,
                           __nv_bfloat16* __restrict__ kh,  __nv_bfloat16* __restrict__ kl,
                           __nv_bfloat16* __restrict__ q2h, __nv_bfloat16* __restrict__ q2l,
                           __nv_bfloat16* __restrict__ k2h, __nv_bfloat16* __restrict__ k2l,
                           __nv_bfloat16* __restrict__ vh,  __nv_bfloat16* __restrict__ vl) {
    const int idx = blockIdx.x * blockDim.x + threadIdx.x;
    const int i = idx & 31;
    const int h = (idx >> 5) & (HH - 1);
    const int t = (idx >> 9) & (TT - 1);
    const int b = idx >> 20;

    const float inv_freq = powf(10000.0f, -(float)i * (1.0f / 32.0f));
    float c, s;
    sincosf((float)t * inv_freq, &s, &c);

    const size_t base = ((size_t)(b * TT + t)) * DD + h * DH + i;

    const float* in[4]  = {q, k, q2, k2};
    __nv_bfloat16* oh[4] = {qh, kh, q2h, k2h};
    __nv_bfloat16* ol[4] = {ql, kl, q2l, k2l};
#pragma unroll
    for (int a = 0; a < 4; a++) {
        float x1 = in[a][base];
        float x2 = in[a][base + 32];
        float y1 = fmaf(x1, c, x2 * s);
        float y2 = fmaf(-x1, s, x2 * c);
        unsigned short hh, lll;
        fsplit(y1, hh, lll);
        oh[a][base]      = __ushort_as_bfloat16(hh);
        ol[a][base]      = __ushort_as_bfloat16(lll);
        fsplit(y2, hh, lll);
        oh[a][base + 32] = __ushort_as_bfloat16(hh);
        ol[a][base + 32] = __ushort_as_bfloat16(lll);
    }
    {
        unsigned short hh, lll;
        float v1 = v[base];
        fsplit(v1, hh, lll);
        vh[base]      = __ushort_as_bfloat16(hh);
        vl[base]      = __ushort_as_bfloat16(lll);
        float v2 = v[base + 32];
        fsplit(v2, hh, lll);
        vh[base + 32] = __ushort_as_bfloat16(hh);
        vl[base + 32] = __ushort_as_bfloat16(lll);
    }
}

// ---------------------------------------------------------------------------
// Tensor-core causal bilinear attention.
// CTA: 128 q rows (8 warps x m16), kv tiles of 64, double-buffered cp.async.
// ---------------------------------------------------------------------------
__global__ void __launch_bounds__(256, 1) attn_mma(
        const __nv_bfloat16* __restrict__ qh,  const __nv_bfloat16* __restrict__ ql,
        const __nv_bfloat16* __restrict__ q2h, const __nv_bfloat16* __restrict__ q2l,
        const __nv_bfloat16* __restrict__ kh,  const __nv_bfloat16* __restrict__ kl,
        const __nv_bfloat16* __restrict__ k2h, const __nv_bfloat16* __restrict__ k2l,
        const __nv_bfloat16* __restrict__ vh,  const __nv_bfloat16* __restrict__ vl,
        float* __restrict__ z) {
    extern __shared__ __nv_bfloat16 sb2[];
    const int tid  = threadIdx.x;
    const int lane = tid & 31;
    const int w    = tid >> 5;
    const int qb = (int)gridDim.x - 1 - (int)blockIdx.x;   // heavy first
    const int q0 = qb * 128;
    const int b  = blockIdx.y >> 4;
    const int h  = blockIdx.y & 15;
    const size_t bh_off = (size_t)b * TT * DD + h * DH;

    // ---- stage Q/Q2 hi/lo tiles and load fragments to registers ----
    {
        const __nv_bfloat16* src[4] = {qh, ql, q2h, q2l};
#pragma unroll
        for (int a = 0; a < 4; a++) {
            __nv_bfloat16* dst = sb2 + a * 128 * KST;
            for (int i = tid; i < 1024; i += 256) {
                const int r = i >> 3, ck = (i & 7) * 8;
                cpa16(dst + r * KST + ck, src[a] + bh_off + (size_t)(q0 + r) * DD + ck);
            }
        }
        cpa_commit();
        cpa_wait0();
        __syncthreads();
    }

    uint32_t fqh[4][4], fql[4][4], fq2h[4][4], fq2l[4][4];
    {
        const int ar = w * 16 + (lane & 15);
        const int ak = (lane >> 4) * 8;
#pragma unroll
        for (int kf = 0; kf < 4; kf++) {
            ldmat_x4(fqh [kf], saddr(sb2 + 0 * 128 * KST + ar * KST + kf * 16 + ak));
            ldmat_x4(fql [kf], saddr(sb2 + 1 * 128 * KST + ar * KST + kf * 16 + ak));
            ldmat_x4(fq2h[kf], saddr(sb2 + 2 * 128 * KST + ar * KST + kf * 16 + ak));
            ldmat_x4(fq2l[kf], saddr(sb2 + 3 * 128 * KST + ar * KST + kf * 16 + ak));
        }
    }
    __syncthreads();   // smem now free for K/V buffers

    float zacc[8][4];
#pragma unroll
    for (int i = 0; i < 8; i++)
#pragma unroll
        for (int j = 0; j < 4; j++) zacc[i][j] = 0.0f;

    const int nkv = 2 * qb + 2;
    const int br = (lane & 7) + ((lane >> 4) & 1) * 8;
    const int bk = ((lane >> 3) & 1) * 8;
    const float invd2 = 1.0f / ((float)DH * (float)DH);

    // ---- tile loader: K,K2 hi/lo via cp.async; V hi/lo manual transpose ----
    auto load_tile = [&](int kj, int buf) {
        __nv_bfloat16* base = sb2 + buf * STAGE;
        const int kv0 = kj * 64;
        const __nv_bfloat16* src[4] = {kh, kl, k2h, k2l};
#pragma unroll
        for (int a = 0; a < 4; a++) {
            __nv_bfloat16* dst = base + a * ATILE;
            for (int i = tid; i < 512; i += 256) {
                const int r = i >> 3, ck = (i & 7) * 8;
                cpa16(dst + r * KST + ck, src[a] + bh_off + (size_t)(kv0 + r) * DD + ck);
            }
        }
        // V transpose: Vt[d][kv]
        {
            const int r  = tid & 63;
            const int dg = (tid >> 6) * 16;
            const __nv_bfloat16* s1p = vh + bh_off + (size_t)(kv0 + r) * DD + dg;
            const __nv_bfloat16* s2p = vl + bh_off + (size_t)(kv0 + r) * DD + dg;
            unsigned short t1[16], t2[16];
            *(uint4*)t1       = *(const uint4*)s1p;
            *(uint4*)(t1 + 8) = *(const uint4*)(s1p + 8);
            *(uint4*)t2       = *(const uint4*)s2p;
            *(uint4*)(t2 + 8) = *(const uint4*)(s2p + 8);
            unsigned short* dh = (unsigned short*)(base + 4 * ATILE);
            unsigned short* dl = (unsigned short*)(base + 5 * ATILE);
#pragma unroll
            for (int j = 0; j < 16; j++) {
                dh[(dg + j) * KST + r] = t1[j];
                dl[(dg + j) * KST + r] = t2[j];
            }
        }
    };

    load_tile(0, 0);
    cpa_commit();

    for (int kj = 0; kj < nkv; kj++) {
        cpa_wait0();
        __syncthreads();
        if (kj + 1 < nkv) {
            load_tile(kj + 1, (kj + 1) & 1);
            cpa_commit();
        }

        const __nv_bfloat16* base = sb2 + (kj & 1) * STAGE;
        const int kv0 = kj * 64;
        const bool masked = (kv0 >= q0);

        uint32_t ph[8][2], pl[8][2];
#pragma unroll
        for (int g = 0; g < 4; g++) {
            float s1f[2][4], s2f[2][4];
#pragma unroll
            for (int p = 0; p < 2; p++)
#pragma unroll
                for (int e = 0; e < 4; e++) { s1f[p][e] = 0.0f; s2f[p][e] = 0.0f; }

#pragma unroll
            for (int kf = 0; kf < 4; kf++) {
                uint32_t bh_[4], bl_[4];
                const int off = (g * 16 + br) * KST + kf * 16 + bk;
                ldmat_x4(bh_, saddr(base + 0 * ATILE + off));
                ldmat_x4(bl_, saddr(base + 1 * ATILE + off));
#pragma unroll
                for (int p = 0; p < 2; p++) {
                    mma16816(s1f[p], fqh[kf], bh_[p*2], bh_[p*2+1]);
                    mma16816(s1f[p], fqh[kf], bl_[p*2], bl_[p*2+1]);
                    mma16816(s1f[p], fql[kf], bh_[p*2], bh_[p*2+1]);
                }
                ldmat_x4(bh_, saddr(base + 2 * ATILE + off));
                ldmat_x4(bl_, saddr(base + 3 * ATILE + off));
#pragma unroll
                for (int p = 0; p < 2; p++) {
                    mma16816(s2f[p], fq2h[kf], bh_[p*2], bh_[p*2+1]);
                    mma16816(s2f[p], fq2h[kf], bl_[p*2], bl_[p*2+1]);
                    mma16816(s2f[p], fq2l[kf], bh_[p*2], bh_[p*2+1]);
                }
            }
            // P = mask(s1*s2)/Dh^2, split hi/lo, pack into A-frag halves
#pragma unroll
            for (int p = 0; p < 2; p++) {
                const int j = g * 2 + p;
                float pr[4];
#pragma unroll
                for (int e = 0; e < 4; e++) pr[e] = s1f[p][e] * s2f[p][e] * invd2;
                if (masked) {
                    const int qr = q0 + w * 16 + (lane >> 2);
                    const int kc = kv0 + j * 8 + (lane & 3) * 2;
                    if (kc     > qr)     pr[0] = 0.0f;
                    if (kc + 1 > qr)     pr[1] = 0.0f;
                    if (kc     > qr + 8) pr[2] = 0.0f;
                    if (kc + 1 > qr + 8) pr[3] = 0.0f;
                }
                unsigned short hh[4], ll[4];
#pragma unroll
                for (int e = 0; e < 4; e++) fsplit(pr[e], hh[e], ll[e]);
                ph[j][0] = (uint32_t)hh[1] << 16 | hh[0];
                ph[j][1] = (uint32_t)hh[3] << 16 | hh[2];
                pl[j][0] = (uint32_t)ll[1] << 16 | ll[0];
                pl[j][1] = (uint32_t)ll[3] << 16 | ll[2];
            }
        }

        // Z += P V  (A = P frags, B = Vt)
#pragma unroll
        for (int f = 0; f < 4; f++) {
            uint32_t ah[4] = {ph[2*f][0], ph[2*f][1], ph[2*f+1][0], ph[2*f+1][1]};
            uint32_t al[4] = {pl[2*f][0], pl[2*f][1], pl[2*f+1][0], pl[2*f+1][1]};
#pragma unroll
            for (int gd = 0; gd < 4; gd++) {
                uint32_t vh_[4], vl_[4];
                const int off = (gd * 16 + br) * KST + f * 16 + bk;
                ldmat_x4(vh_, saddr(base + 4 * ATILE + off));
                ldmat_x4(vl_, saddr(base + 5 * ATILE + off));
#pragma unroll
                for (int p = 0; p < 2; p++) {
                    mma16816(zacc[gd*2+p], ah, vh_[p*2], vh_[p*2+1]);
                    mma16816(zacc[gd*2+p], ah, vl_[p*2], vl_[p*2+1]);
                    mma16816(zacc[gd*2+p], al, vh_[p*2], vh_[p*2+1]);
                }
            }
        }
        __syncthreads();
    }

    // epilogue: z fp32 [B,T,H,Dh]
    {
        const int r = q0 + w * 16 + (lane >> 2);
        const int c = (lane & 3) * 2;
#pragma unroll
        for (int nd = 0; nd < 8; nd++) {
            *(float2*)(z + bh_off + (size_t)r * DD + nd * 8 + c) =
                make_float2(zacc[nd][0], zacc[nd][1]);
            *(float2*)(z + bh_off + (size_t)(r + 8) * DD + nd * 8 + c) =
                make_float2(zacc[nd][2], zacc[nd][3]);
        }
    }
}

// ---------------------------------------------------------------------------
extern "C" void kernel_launch(void* const* d_in, const int* in_sizes, int n_in,
                              void* d_out, int out_size) {
    const float* x     = (const float*)d_in[0];
    const float* Wq    = (const float*)d_in[1];
    const float* Wk    = (const float*)d_in[2];
    const float* Wq2   = (const float*)d_in[3];
    const float* Wk2   = (const float*)d_in[4];
    const float* Wv    = (const float*)d_in[5];
    const float* Wproj = (const float*)d_in[6];
    float* out = (float*)d_out;

    float *q, *k, *q2, *k2, *v, *z;
    cudaGetSymbolAddress((void**)&q,  g_q);
    cudaGetSymbolAddress((void**)&k,  g_k);
    cudaGetSymbolAddress((void**)&q2, g_q2);
    cudaGetSymbolAddress((void**)&k2, g_k2);
    cudaGetSymbolAddress((void**)&v,  g_v);
    cudaGetSymbolAddress((void**)&z,  g_z);

    __nv_bfloat16 *qh, *ql, *q2h, *q2l, *kh, *kl, *k2h, *k2l, *vh, *vl;
    cudaGetSymbolAddress((void**)&qh,  g_qh);  cudaGetSymbolAddress((void**)&ql,  g_ql);
    cudaGetSymbolAddress((void**)&q2h, g_q2h); cudaGetSymbolAddress((void**)&q2l, g_q2l);
    cudaGetSymbolAddress((void**)&kh,  g_kh);  cudaGetSymbolAddress((void**)&kl,  g_kl);
    cudaGetSymbolAddress((void**)&k2h, g_k2h); cudaGetSymbolAddress((void**)&k2l, g_k2l);
    cudaGetSymbolAddress((void**)&vh,  g_vh);  cudaGetSymbolAddress((void**)&vl,  g_vl);

    const dim3 ggrid(DD / 128, MM / 128);
    const int gemm_smem = 2 * BUFE * (int)sizeof(__nv_bfloat16);   // 81920 B
    cudaFuncSetAttribute(gemm_mma,
                         cudaFuncAttributeMaxDynamicSharedMemorySize, gemm_smem);

    gemm_mma<<<ggrid, 256, gemm_smem>>>(x, Wq,  q);
    gemm_mma<<<ggrid, 256, gemm_smem>>>(x, Wk,  k);
    gemm_mma<<<ggrid, 256, gemm_smem>>>(x, Wq2, q2);
    gemm_mma<<<ggrid, 256, gemm_smem>>>(x, Wk2, k2);
    gemm_mma<<<ggrid, 256, gemm_smem>>>(x, Wv,  v);

    rope_split<<<(BB * TT * HH * 32) / 256, 256>>>(q, k, q2, k2, v,
                                                   qh, ql, kh, kl,
                                                   q2h, q2l, k2h, k2l, vh, vl);

    const int attn_smem = 2 * STAGE * (int)sizeof(__nv_bfloat16);  // 110592 B
    cudaFuncSetAttribute(attn_mma,
                         cudaFuncAttributeMaxDynamicSharedMemorySize, attn_smem);
    attn_mma<<<dim3(TT / 128, BB * HH), 256, attn_smem>>>(
        qh, ql, q2h, q2l, kh, kl, k2h, k2l, vh, vl, z);

    gemm_mma<<<ggrid, 256, gemm_smem>>>(z, Wproj, out);
}

// round 4
// speedup vs baseline: 2.7435x; 1.1565x over previous
#include <cuda_runtime.h>
#include <cuda_bf16.h>
#include <math.h>
#include <stdint.h>

#define BB 2
#define TT 2048
#define DD 1024
#define HH 16
#define DH 64
#define MM (BB*TT)

#define GST 40            /* gemm smem row stride (bf16), 80B */
#define GTILE (128*GST)   /* 5120 bf16 per 128x32 tile */
#define GSTAGE (4*GTILE)  /* Ah,Al,Wh,Wl per stage */
#define NST 4             /* pipeline stages */

#define KST 72            /* attn smem row stride (bf16) */
#define ATILE (64*KST)
#define STAGE (6*ATILE)

// ---------------- scratch (device globals) ----------------------------------
__device__ float g_p5[5*MM*DD];            // q,k,q2,k2,v projections (fp32)
__device__ float g_z [MM*DD];
__device__ __nv_bfloat16 g_xh [MM*DD], g_xl [MM*DD];
__device__ __nv_bfloat16 g_zh [MM*DD], g_zl [MM*DD];
__device__ __nv_bfloat16 g_w6h[6*DD*DD], g_w6l[6*DD*DD];
__device__ __nv_bfloat16 g_qh [MM*DD], g_ql [MM*DD];
__device__ __nv_bfloat16 g_q2h[MM*DD], g_q2l[MM*DD];
__device__ __nv_bfloat16 g_kh [MM*DD], g_kl [MM*DD];
__device__ __nv_bfloat16 g_k2h[MM*DD], g_k2l[MM*DD];
__device__ __nv_bfloat16 g_vh [MM*DD], g_vl [MM*DD];

// ---------------------------------------------------------------------------
__device__ __forceinline__ uint32_t saddr(const void* p) {
    return (uint32_t)__cvta_generic_to_shared(p);
}
__device__ __forceinline__ void ldmat_x4(uint32_t (&r)[4], uint32_t a) {
    asm volatile("ldmatrix.sync.aligned.m8n8.x4.shared.b16 {%0,%1,%2,%3}, [%4];"
                 : "=r"(r[0]), "=r"(r[1]), "=r"(r[2]), "=r"(r[3]) : "r"(a));
}
__device__ __forceinline__ void mma16816(float (&d)[4], const uint32_t (&a)[4],
                                         uint32_t b0, uint32_t b1) {
    asm volatile(
        "mma.sync.aligned.m16n8k16.row.col.f32.bf16.bf16.f32 "
        "{%0,%1,%2,%3}, {%4,%5,%6,%7}, {%8,%9}, {%0,%1,%2,%3};"
        : "+f"(d[0]), "+f"(d[1]), "+f"(d[2]), "+f"(d[3])
        : "r"(a[0]), "r"(a[1]), "r"(a[2]), "r"(a[3]), "r"(b0), "r"(b1));
}
__device__ __forceinline__ void cpa16(void* dst, const void* src) {
    asm volatile("cp.async.cg.shared.global [%0], [%1], 16;"
                 :: "r"(saddr(dst)), "l"(src));
}
__device__ __forceinline__ void cpa_commit() { asm volatile("cp.async.commit_group;"); }
__device__ __forceinline__ void cpa_wait0()  { asm volatile("cp.async.wait_group 0;"); }
__device__ __forceinline__ void cpa_wait2()  { asm volatile("cp.async.wait_group 2;"); }

__device__ __forceinline__ void fsplit(float x, unsigned short& h, unsigned short& l) {
    __nv_bfloat16 hb = __float2bfloat16_rn(x);
    __nv_bfloat16 lb = __float2bfloat16_rn(x - __bfloat162float(hb));
    h = __bfloat16_as_ushort(hb);
    l = __bfloat16_as_ushort(lb);
}

// ---------------------------------------------------------------------------
// elementwise fp32 -> bf16 hi/lo split
// ---------------------------------------------------------------------------
__global__ void split_f32(const float* __restrict__ in,
                          __nv_bfloat16* __restrict__ hi,
                          __nv_bfloat16* __restrict__ lo) {
    const size_t i = ((size_t)blockIdx.x * 256 + threadIdx.x) * 4;
    float4 v = *(const float4*)(in + i);
    float f[4] = {v.x, v.y, v.z, v.w};
    unsigned short h[4], l[4];
#pragma unroll
    for (int e = 0; e < 4; e++) fsplit(f[e], h[e], l[e]);
    *(uint2*)(hi + i) = make_uint2((uint32_t)h[1] << 16 | h[0],
                                   (uint32_t)h[3] << 16 | h[2]);
    *(uint2*)(lo + i) = make_uint2((uint32_t)l[1] << 16 | l[0],
                                   (uint32_t)l[3] << 16 | l[2]);
}

// split all six weight matrices into contiguous hi/lo buffers
__global__ void split_w6(const float* __restrict__ w0, const float* __restrict__ w1,
                         const float* __restrict__ w2, const float* __restrict__ w3,
                         const float* __restrict__ w4, const float* __restrict__ w5,
                         __nv_bfloat16* __restrict__ hi, __nv_bfloat16* __restrict__ lo) {
    const float* src[6] = {w0, w1, w2, w3, w4, w5};
    const float* in = src[blockIdx.y];
    const size_t off = (size_t)blockIdx.y * DD * DD;
    const size_t i = ((size_t)blockIdx.x * 256 + threadIdx.x) * 4;
    float4 v = *(const float4*)(in + i);
    float f[4] = {v.x, v.y, v.z, v.w};
    unsigned short h[4], l[4];
#pragma unroll
    for (int e = 0; e < 4; e++) fsplit(f[e], h[e], l[e]);
    *(uint2*)(hi + off + i) = make_uint2((uint32_t)h[1] << 16 | h[0],
                                         (uint32_t)h[3] << 16 | h[2]);
    *(uint2*)(lo + off + i) = make_uint2((uint32_t)l[1] << 16 | l[0],
                                         (uint32_t)l[3] << 16 | l[2]);
}

// ---------------------------------------------------------------------------
// C[M,N] = A[M,K] @ W[N,K]^T, pre-split bf16 hi/lo inputs, 3x mma,
// cp.async 4-stage pipeline. blockIdx.z selects weight slice + output slice.
// ---------------------------------------------------------------------------
__global__ void __launch_bounds__(256, 1) gemm_bf16(
        const __nv_bfloat16* __restrict__ Ah, const __nv_bfloat16* __restrict__ Al,
        const __nv_bfloat16* __restrict__ Wh, const __nv_bfloat16* __restrict__ Wl,
        float* __restrict__ C) {
    extern __shared__ __nv_bfloat16 sg[];
    const int zi = blockIdx.z;
    Wh += (size_t)zi * DD * DD;
    Wl += (size_t)zi * DD * DD;
    C  += (size_t)zi * MM * DD;

    const int tid  = threadIdx.x;
    const int wid  = tid >> 5;
    const int lane = tid & 31;
    const int m0 = blockIdx.y * 128;
    const int n0 = blockIdx.x * 128;
    const int wm = wid & 1;
    const int wn = wid >> 1;

    auto load_stage = [&](int s) {
        __nv_bfloat16* base = sg + (s & (NST - 1)) * GSTAGE;
        const int k0 = s * 32;
#pragma unroll 2
        for (int i = tid; i < 512; i += 256) {
            const int r = i >> 2, ck = (i & 3) * 8;
            cpa16(base + 0 * GTILE + r * GST + ck, Ah + (size_t)(m0 + r) * DD + k0 + ck);
            cpa16(base + 1 * GTILE + r * GST + ck, Al + (size_t)(m0 + r) * DD + k0 + ck);
            cpa16(base + 2 * GTILE + r * GST + ck, Wh + (size_t)(n0 + r) * DD + k0 + ck);
            cpa16(base + 3 * GTILE + r * GST + ck, Wl + (size_t)(n0 + r) * DD + k0 + ck);
        }
        cpa_commit();
    };

    float acc[4][4][4];
#pragma unroll
    for (int i = 0; i < 4; i++)
#pragma unroll
        for (int j = 0; j < 4; j++)
#pragma unroll
            for (int c = 0; c < 4; c++) acc[i][j][c] = 0.0f;

    load_stage(0);
    load_stage(1);
    load_stage(2);

    for (int s = 0; s < 32; s++) {
        cpa_wait2();           // stage s resident (this thread)
        __syncthreads();       // stage s resident (all threads)
        if (s + 3 < 32) load_stage(s + 3);
        else            cpa_commit();   // keep group-count invariant

        const __nv_bfloat16* cur = sg + (s & (NST - 1)) * GSTAGE;
        const __nv_bfloat16* Ahi = cur;
        const __nv_bfloat16* Alo = cur + GTILE;
        const __nv_bfloat16* Bhi = cur + 2 * GTILE;
        const __nv_bfloat16* Blo = cur + 3 * GTILE;

#pragma unroll
        for (int kk = 0; kk < 2; kk++) {
            uint32_t ahi[4][4], alo[4][4], bhi[2][4], blo[2][4];
            const int ar = wm * 64 + (lane & 15);
            const int ak = kk * 16 + (lane >> 4) * 8;
#pragma unroll
            for (int mi = 0; mi < 4; mi++) {
                ldmat_x4(ahi[mi], saddr(Ahi + (ar + mi * 16) * GST + ak));
                ldmat_x4(alo[mi], saddr(Alo + (ar + mi * 16) * GST + ak));
            }
            const int br = wn * 32 + ((lane >> 4) & 1) * 8 + (lane & 7);
            const int bk = kk * 16 + ((lane >> 3) & 1) * 8;
#pragma unroll
            for (int p = 0; p < 2; p++) {
                ldmat_x4(bhi[p], saddr(Bhi + (br + p * 16) * GST + bk));
                ldmat_x4(blo[p], saddr(Blo + (br + p * 16) * GST + bk));
            }
#pragma unroll
            for (int mi = 0; mi < 4; mi++)
#pragma unroll
                for (int ni = 0; ni < 4; ni++) {
                    const uint32_t* bh = &bhi[ni >> 1][(ni & 1) * 2];
                    const uint32_t* bl = &blo[ni >> 1][(ni & 1) * 2];
                    mma16816(acc[mi][ni], ahi[mi], bh[0], bh[1]);
                    mma16816(acc[mi][ni], ahi[mi], bl[0], bl[1]);
                    mma16816(acc[mi][ni], alo[mi], bh[0], bh[1]);
                }
        }
    }

#pragma unroll
    for (int mi = 0; mi < 4; mi++)
#pragma unroll
        for (int ni = 0; ni < 4; ni++) {
            const int r0 = m0 + wm * 64 + mi * 16 + (lane >> 2);
            const int c0 = n0 + wn * 32 + ni * 8 + (lane & 3) * 2;
            *(float2*)(C + (size_t)r0 * 1024 + c0) =
                make_float2(acc[mi][ni][0], acc[mi][ni][1]);
            *(float2*)(C + (size_t)(r0 + 8) * 1024 + c0) =
                make_float2(acc[mi][ni][2], acc[mi][ni][3]);
        }
}

// ---------------------------------------------------------------------------
// RoPE + split to bf16 hi/lo; reads from contiguous p5 (q,k,q2,k2,v)
// ---------------------------------------------------------------------------
__global__ void rope_split(const float* __restrict__ p5,
                           __nv_bfloat16* __restrict__ qh,  __nv_bfloat16* __restrict__ ql,
                           __nv_bfloat16* __restrict__ kh,  __nv_bfloat16* __restrict__ kl,
                           __nv_bfloat16* __restrict__ q2h, __nv_bfloat16* __restrict__ q2l,
                           __nv_bfloat16* __restrict__ k2h, __nv_bfloat16* __restrict__ k2l,
                           __nv_bfloat16* __restrict__ vh,  __nv_bfloat16* __restrict__ vl) {
    const int idx = blockIdx.x * blockDim.x + threadIdx.x;
    const int i = idx & 31;
    const int h = (idx >> 5) & (HH - 1);
    const int t = (idx >> 9) & (TT - 1);
    const int b = idx >> 20;

    const float inv_freq = powf(10000.0f, -(float)i * (1.0f / 32.0f));
    float c, s;
    sincosf((float)t * inv_freq, &s, &c);

    const size_t base = ((size_t)(b * TT + t)) * DD + h * DH + i;

    __nv_bfloat16* oh[4] = {qh, kh, q2h, k2h};
    __nv_bfloat16* ol[4] = {ql, kl, q2l, k2l};
#pragma unroll
    for (int a = 0; a < 4; a++) {
        const float* in = p5 + (size_t)a * MM * DD;
        float x1 = in[base];
        float x2 = in[base + 32];
        float y1 = fmaf(x1, c, x2 * s);
        float y2 = fmaf(-x1, s, x2 * c);
        unsigned short hh, lll;
        fsplit(y1, hh, lll);
        oh[a][base]      = __ushort_as_bfloat16(hh);
        ol[a][base]      = __ushort_as_bfloat16(lll);
        fsplit(y2, hh, lll);
        oh[a][base + 32] = __ushort_as_bfloat16(hh);
        ol[a][base + 32] = __ushort_as_bfloat16(lll);
    }
    {
        const float* vv = p5 + (size_t)4 * MM * DD;
        unsigned short hh, lll;
        fsplit(vv[base], hh, lll);
        vh[base]      = __ushort_as_bfloat16(hh);
        vl[base]      = __ushort_as_bfloat16(lll);
        fsplit(vv[base + 32], hh, lll);
        vh[base + 32] = __ushort_as_bfloat16(hh);
        vl[base + 32] = __ushort_as_bfloat16(lll);
    }
}

// ---------------------------------------------------------------------------
// Tensor-core causal bilinear attention (unchanged from round 3).
// ---------------------------------------------------------------------------
__global__ void __launch_bounds__(256, 1) attn_mma(
        const __nv_bfloat16* __restrict__ qh,  const __nv_bfloat16* __restrict__ ql,
        const __nv_bfloat16* __restrict__ q2h, const __nv_bfloat16* __restrict__ q2l,
        const __nv_bfloat16* __restrict__ kh,  const __nv_bfloat16* __restrict__ kl,
        const __nv_bfloat16* __restrict__ k2h, const __nv_bfloat16* __restrict__ k2l,
        const __nv_bfloat16* __restrict__ vh,  const __nv_bfloat16* __restrict__ vl,
        float* __restrict__ z) {
    extern __shared__ __nv_bfloat16 sb2[];
    const int tid  = threadIdx.x;
    const int lane = tid & 31;
    const int w    = tid >> 5;
    const int qb = (int)gridDim.x - 1 - (int)blockIdx.x;
    const int q0 = qb * 128;
    const int b  = blockIdx.y >> 4;
    const int h  = blockIdx.y & 15;
    const size_t bh_off = (size_t)b * TT * DD + h * DH;

    {
        const __nv_bfloat16* src[4] = {qh, ql, q2h, q2l};
#pragma unroll
        for (int a = 0; a < 4; a++) {
            __nv_bfloat16* dst = sb2 + a * 128 * KST;
            for (int i = tid; i < 1024; i += 256) {
                const int r = i >> 3, ck = (i & 7) * 8;
                cpa16(dst + r * KST + ck, src[a] + bh_off + (size_t)(q0 + r) * DD + ck);
            }
        }
        cpa_commit();
        cpa_wait0();
        __syncthreads();
    }

    uint32_t fqh[4][4], fql[4][4], fq2h[4][4], fq2l[4][4];
    {
        const int ar = w * 16 + (lane & 15);
        const int ak = (lane >> 4) * 8;
#pragma unroll
        for (int kf = 0; kf < 4; kf++) {
            ldmat_x4(fqh [kf], saddr(sb2 + 0 * 128 * KST + ar * KST + kf * 16 + ak));
            ldmat_x4(fql [kf], saddr(sb2 + 1 * 128 * KST + ar * KST + kf * 16 + ak));
            ldmat_x4(fq2h[kf], saddr(sb2 + 2 * 128 * KST + ar * KST + kf * 16 + ak));
            ldmat_x4(fq2l[kf], saddr(sb2 + 3 * 128 * KST + ar * KST + kf * 16 + ak));
        }
    }
    __syncthreads();

    float zacc[8][4];
#pragma unroll
    for (int i = 0; i < 8; i++)
#pragma unroll
        for (int j = 0; j < 4; j++) zacc[i][j] = 0.0f;

    const int nkv = 2 * qb + 2;
    const int br = (lane & 7) + ((lane >> 4) & 1) * 8;
    const int bk = ((lane >> 3) & 1) * 8;
    const float invd2 = 1.0f / ((float)DH * (float)DH);

    auto load_tile = [&](int kj, int buf) {
        __nv_bfloat16* base = sb2 + buf * STAGE;
        const int kv0 = kj * 64;
        const __nv_bfloat16* src[4] = {kh, kl, k2h, k2l};
#pragma unroll
        for (int a = 0; a < 4; a++) {
            __nv_bfloat16* dst = base + a * ATILE;
            for (int i = tid; i < 512; i += 256) {
                const int r = i >> 3, ck = (i & 7) * 8;
                cpa16(dst + r * KST + ck, src[a] + bh_off + (size_t)(kv0 + r) * DD + ck);
            }
        }
        {
            const int r  = tid & 63;
            const int dg = (tid >> 6) * 16;
            const __nv_bfloat16* s1p = vh + bh_off + (size_t)(kv0 + r) * DD + dg;
            const __nv_bfloat16* s2p = vl + bh_off + (size_t)(kv0 + r) * DD + dg;
            unsigned short t1[16], t2[16];
            *(uint4*)t1       = *(const uint4*)s1p;
            *(uint4*)(t1 + 8) = *(const uint4*)(s1p + 8);
            *(uint4*)t2       = *(const uint4*)s2p;
            *(uint4*)(t2 + 8) = *(const uint4*)(s2p + 8);
            unsigned short* dh = (unsigned short*)(base + 4 * ATILE);
            unsigned short* dl = (unsigned short*)(base + 5 * ATILE);
#pragma unroll
            for (int j = 0; j < 16; j++) {
                dh[(dg + j) * KST + r] = t1[j];
                dl[(dg + j) * KST + r] = t2[j];
            }
        }
    };

    load_tile(0, 0);
    cpa_commit();

    for (int kj = 0; kj < nkv; kj++) {
        cpa_wait0();
        __syncthreads();
        if (kj + 1 < nkv) {
            load_tile(kj + 1, (kj + 1) & 1);
            cpa_commit();
        }

        const __nv_bfloat16* base = sb2 + (kj & 1) * STAGE;
        const int kv0 = kj * 64;
        const bool masked = (kv0 >= q0);

        uint32_t ph[8][2], pl[8][2];
#pragma unroll
        for (int g = 0; g < 4; g++) {
            float s1f[2][4], s2f[2][4];
#pragma unroll
            for (int p = 0; p < 2; p++)
#pragma unroll
                for (int e = 0; e < 4; e++) { s1f[p][e] = 0.0f; s2f[p][e] = 0.0f; }

#pragma unroll
            for (int kf = 0; kf < 4; kf++) {
                uint32_t bh_[4], bl_[4];
                const int off = (g * 16 + br) * KST + kf * 16 + bk;
                ldmat_x4(bh_, saddr(base + 0 * ATILE + off));
                ldmat_x4(bl_, saddr(base + 1 * ATILE + off));
#pragma unroll
                for (int p = 0; p < 2; p++) {
                    mma16816(s1f[p], fqh[kf], bh_[p*2], bh_[p*2+1]);
                    mma16816(s1f[p], fqh[kf], bl_[p*2], bl_[p*2+1]);
                    mma16816(s1f[p], fql[kf], bh_[p*2], bh_[p*2+1]);
                }
                ldmat_x4(bh_, saddr(base + 2 * ATILE + off));
                ldmat_x4(bl_, saddr(base + 3 * ATILE + off));
#pragma unroll
                for (int p = 0; p < 2; p++) {
                    mma16816(s2f[p], fq2h[kf], bh_[p*2], bh_[p*2+1]);
                    mma16816(s2f[p], fq2h[kf], bl_[p*2], bl_[p*2+1]);
                    mma16816(s2f[p], fq2l[kf], bh_[p*2], bh_[p*2+1]);
                }
            }
#pragma unroll
            for (int p = 0; p < 2; p++) {
                const int j = g * 2 + p;
                float pr[4];
#pragma unroll
                for (int e = 0; e < 4; e++) pr[e] = s1f[p][e] * s2f[p][e] * invd2;
                if (masked) {
                    const int qr = q0 + w * 16 + (lane >> 2);
                    const int kc = kv0 + j * 8 + (lane & 3) * 2;
                    if (kc     > qr)     pr[0] = 0.0f;
                    if (kc + 1 > qr)     pr[1] = 0.0f;
                    if (kc     > qr + 8) pr[2] = 0.0f;
                    if (kc + 1 > qr + 8) pr[3] = 0.0f;
                }
                unsigned short hh[4], ll[4];
#pragma unroll
                for (int e = 0; e < 4; e++) fsplit(pr[e], hh[e], ll[e]);
                ph[j][0] = (uint32_t)hh[1] << 16 | hh[0];
                ph[j][1] = (uint32_t)hh[3] << 16 | hh[2];
                pl[j][0] = (uint32_t)ll[1] << 16 | ll[0];
                pl[j][1] = (uint32_t)ll[3] << 16 | ll[2];
            }
        }

#pragma unroll
        for (int f = 0; f < 4; f++) {
            uint32_t ah[4] = {ph[2*f][0], ph[2*f][1], ph[2*f+1][0], ph[2*f+1][1]};
            uint32_t al[4] = {pl[2*f][0], pl[2*f][1], pl[2*f+1][0], pl[2*f+1][1]};
#pragma unroll
            for (int gd = 0; gd < 4; gd++) {
                uint32_t vh_[4], vl_[4];
                const int off = (gd * 16 + br) * KST + f * 16 + bk;
                ldmat_x4(vh_, saddr(base + 4 * ATILE + off));
                ldmat_x4(vl_, saddr(base + 5 * ATILE + off));
#pragma unroll
                for (int p = 0; p < 2; p++) {
                    mma16816(zacc[gd*2+p], ah, vh_[p*2], vh_[p*2+1]);
                    mma16816(zacc[gd*2+p], ah, vl_[p*2], vl_[p*2+1]);
                    mma16816(zacc[gd*2+p], al, vh_[p*2], vh_[p*2+1]);
                }
            }
        }
        __syncthreads();
    }

    {
        const int r = q0 + w * 16 + (lane >> 2);
        const int c = (lane & 3) * 2;
#pragma unroll
        for (int nd = 0; nd < 8; nd++) {
            *(float2*)(z + bh_off + (size_t)r * DD + nd * 8 + c) =
                make_float2(zacc[nd][0], zacc[nd][1]);
            *(float2*)(z + bh_off + (size_t)(r + 8) * DD + nd * 8 + c) =
                make_float2(zacc[nd][2], zacc[nd][3]);
        }
    }
}

// ---------------------------------------------------------------------------
extern "C" void kernel_launch(void* const* d_in, const int* in_sizes, int n_in,
                              void* d_out, int out_size) {
    const float* x     = (const float*)d_in[0];
    const float* Wq    = (const float*)d_in[1];
    const float* Wk    = (const float*)d_in[2];
    const float* Wq2   = (const float*)d_in[3];
    const float* Wk2   = (const float*)d_in[4];
    const float* Wv    = (const float*)d_in[5];
    const float* Wproj = (const float*)d_in[6];
    float* out = (float*)d_out;

    float *p5, *z;
    cudaGetSymbolAddress((void**)&p5, g_p5);
    cudaGetSymbolAddress((void**)&z,  g_z);

    __nv_bfloat16 *xh, *xl, *zh, *zl, *w6h, *w6l;
    cudaGetSymbolAddress((void**)&xh,  g_xh);  cudaGetSymbolAddress((void**)&xl,  g_xl);
    cudaGetSymbolAddress((void**)&zh,  g_zh);  cudaGetSymbolAddress((void**)&zl,  g_zl);
    cudaGetSymbolAddress((void**)&w6h, g_w6h); cudaGetSymbolAddress((void**)&w6l, g_w6l);

    __nv_bfloat16 *qh, *ql, *q2h, *q2l, *kh, *kl, *k2h, *k2l, *vh, *vl;
    cudaGetSymbolAddress((void**)&qh,  g_qh);  cudaGetSymbolAddress((void**)&ql,  g_ql);
    cudaGetSymbolAddress((void**)&q2h, g_q2h); cudaGetSymbolAddress((void**)&q2l, g_q2l);
    cudaGetSymbolAddress((void**)&kh,  g_kh);  cudaGetSymbolAddress((void**)&kl,  g_kl);
    cudaGetSymbolAddress((void**)&k2h, g_k2h); cudaGetSymbolAddress((void**)&k2l, g_k2l);
    cudaGetSymbolAddress((void**)&vh,  g_vh);  cudaGetSymbolAddress((void**)&vl,  g_vl);

    const int gemm_smem = NST * GSTAGE * (int)sizeof(__nv_bfloat16);  // 163840 B
    cudaFuncSetAttribute(gemm_bf16,
                         cudaFuncAttributeMaxDynamicSharedMemorySize, gemm_smem);

    // 1) split inputs
    split_f32<<<MM * DD / 1024, 256>>>(x, xh, xl);
    split_w6<<<dim3(DD * DD / 1024, 6), 256>>>(Wq, Wk, Wq2, Wk2, Wv, Wproj, w6h, w6l);

    // 2) five fused projections
    gemm_bf16<<<dim3(DD / 128, MM / 128, 5), 256, gemm_smem>>>(xh, xl, w6h, w6l, p5);

    // 3) rope + split
    rope_split<<<(BB * TT * HH * 32) / 256, 256>>>(p5, qh, ql, kh, kl,
                                                   q2h, q2l, k2h, k2l, vh, vl);

    // 4) attention
    const int attn_smem = 2 * STAGE * (int)sizeof(__nv_bfloat16);  // 110592 B
    cudaFuncSetAttribute(attn_mma,
                         cudaFuncAttributeMaxDynamicSharedMemorySize, attn_smem);
    attn_mma<<<dim3(TT / 128, BB * HH), 256, attn_smem>>>(
        qh, ql, q2h, q2l, kh, kl, k2h, k2l, vh, vl, z);

    // 5) output projection
    split_f32<<<MM * DD / 1024, 256>>>(z, zh, zl);
    gemm_bf16<<<dim3(DD / 128, MM / 128, 1), 256, gemm_smem>>>(
        zh, zl, w6h + (size_t)5 * DD * DD, w6l + (size_t)5 * DD * DD, out);
}

// round 6
// speedup vs baseline: 2.9326x; 1.0689x over previous
#include <cuda_runtime.h>
#include <cuda_bf16.h>
#include <math.h>
#include <stdint.h>

#define BB 2
#define TT 2048
#define DD 1024
#define HH 16
#define DH 64
#define MM (BB*TT)

/* ---- gemm geometry: k-chunk 64, 3-stage cp.async pipeline ---- */
#define GST 72              /* smem row stride in bf16 (144B, conflict-free) */
#define GTILE (128*GST)     /* one 128x64 operand tile */
#define GSTAGE (4*GTILE)    /* Ah,Al,Wh,Wl per stage */
#define NSTG 3
#define NCH  16             /* 1024 / 64 */
#define GEMM_SMEM (NSTG*GSTAGE*2)   /* 221184 B */

#define KST 72              /* attn smem row stride (bf16) */
#define ATILE (64*KST)
#define STAGE (6*ATILE)

// ---------------- scratch (device globals) ----------------------------------
__device__ float g_p5[5*MM*DD];
__device__ __nv_bfloat16 g_xh [MM*DD], g_xl [MM*DD];
__device__ __nv_bfloat16 g_zh [MM*DD], g_zl [MM*DD];
__device__ __nv_bfloat16 g_w6h[6*DD*DD], g_w6l[6*DD*DD];
__device__ __nv_bfloat16 g_qh [MM*DD], g_ql [MM*DD];
__device__ __nv_bfloat16 g_q2h[MM*DD], g_q2l[MM*DD];
__device__ __nv_bfloat16 g_kh [MM*DD], g_kl [MM*DD];
__device__ __nv_bfloat16 g_k2h[MM*DD], g_k2l[MM*DD];
__device__ __nv_bfloat16 g_vh [MM*DD], g_vl [MM*DD];

// ---------------------------------------------------------------------------
__device__ __forceinline__ uint32_t saddr(const void* p) {
    return (uint32_t)__cvta_generic_to_shared(p);
}
__device__ __forceinline__ void ldmat_x4(uint32_t (&r)[4], uint32_t a) {
    asm volatile("ldmatrix.sync.aligned.m8n8.x4.shared.b16 {%0,%1,%2,%3}, [%4];"
                 : "=r"(r[0]), "=r"(r[1]), "=r"(r[2]), "=r"(r[3]) : "r"(a));
}
__device__ __forceinline__ void mma16816(float (&d)[4], const uint32_t (&a)[4],
                                         uint32_t b0, uint32_t b1) {
    asm volatile(
        "mma.sync.aligned.m16n8k16.row.col.f32.bf16.bf16.f32 "
        "{%0,%1,%2,%3}, {%4,%5,%6,%7}, {%8,%9}, {%0,%1,%2,%3};"
        : "+f"(d[0]), "+f"(d[1]), "+f"(d[2]), "+f"(d[3])
        : "r"(a[0]), "r"(a[1]), "r"(a[2]), "r"(a[3]), "r"(b0), "r"(b1));
}
__device__ __forceinline__ void cpa16(void* dst, const void* src) {
    asm volatile("cp.async.cg.shared.global [%0], [%1], 16;"
                 :: "r"(saddr(dst)), "l"(src));
}
__device__ __forceinline__ void cpa_commit() { asm volatile("cp.async.commit_group;"); }
__device__ __forceinline__ void cpa_wait0()  { asm volatile("cp.async.wait_group 0;"); }
__device__ __forceinline__ void cpa_wait1()  { asm volatile("cp.async.wait_group 1;"); }

__device__ __forceinline__ void fsplit(float x, unsigned short& h, unsigned short& l) {
    __nv_bfloat16 hb = __float2bfloat16_rn(x);
    __nv_bfloat16 lb = __float2bfloat16_rn(x - __bfloat162float(hb));
    h = __bfloat16_as_ushort(hb);
    l = __bfloat16_as_ushort(lb);
}

// ---------------------------------------------------------------------------
// splits
// ---------------------------------------------------------------------------
__global__ void split_f32(const float* __restrict__ in,
                          __nv_bfloat16* __restrict__ hi,
                          __nv_bfloat16* __restrict__ lo) {
    const size_t i = ((size_t)blockIdx.x * 256 + threadIdx.x) * 4;
    float4 v = *(const float4*)(in + i);
    float f[4] = {v.x, v.y, v.z, v.w};
    unsigned short h[4], l[4];
#pragma unroll
    for (int e = 0; e < 4; e++) fsplit(f[e], h[e], l[e]);
    *(uint2*)(hi + i) = make_uint2((uint32_t)h[1] << 16 | h[0],
                                   (uint32_t)h[3] << 16 | h[2]);
    *(uint2*)(lo + i) = make_uint2((uint32_t)l[1] << 16 | l[0],
                                   (uint32_t)l[3] << 16 | l[2]);
}

__global__ void split_w6(const float* __restrict__ w0, const float* __restrict__ w1,
                         const float* __restrict__ w2, const float* __restrict__ w3,
                         const float* __restrict__ w4, const float* __restrict__ w5,
                         __nv_bfloat16* __restrict__ hi, __nv_bfloat16* __restrict__ lo) {
    const float* src[6] = {w0, w1, w2, w3, w4, w5};
    const float* in = src[blockIdx.y];
    const size_t off = (size_t)blockIdx.y * DD * DD;
    const size_t i = ((size_t)blockIdx.x * 256 + threadIdx.x) * 4;
    float4 v = *(const float4*)(in + i);
    float f[4] = {v.x, v.y, v.z, v.w};
    unsigned short h[4], l[4];
#pragma unroll
    for (int e = 0; e < 4; e++) fsplit(f[e], h[e], l[e]);
    *(uint2*)(hi + off + i) = make_uint2((uint32_t)h[1] << 16 | h[0],
                                         (uint32_t)h[3] << 16 | h[2]);
    *(uint2*)(lo + off + i) = make_uint2((uint32_t)l[1] << 16 | l[0],
                                         (uint32_t)l[3] << 16 | l[2]);
}

// ---------------------------------------------------------------------------
// C[M,N] = A[M,K] @ W[N,K]^T, bf16 hi/lo 3-term mma.sync.
// 128x128 CTA tile, k-chunk 64, 3-stage cp.async pipeline, 256 threads.
// ---------------------------------------------------------------------------
__global__ void __launch_bounds__(256, 1) gemm_bf16(
        const __nv_bfloat16* __restrict__ Ah, const __nv_bfloat16* __restrict__ Al,
        const __nv_bfloat16* __restrict__ Wh, const __nv_bfloat16* __restrict__ Wl,
        float* __restrict__ C) {
    extern __shared__ __nv_bfloat16 sg[];
    const int zi = blockIdx.z;
    Wh += (size_t)zi * DD * DD;
    Wl += (size_t)zi * DD * DD;
    C  += (size_t)zi * MM * DD;

    const int tid  = threadIdx.x;
    const int wid  = tid >> 5;
    const int lane = tid & 31;
    const int m0 = blockIdx.y * 128;
    const int n0 = blockIdx.x * 128;
    const int wm = wid & 1;
    const int wn = wid >> 1;

    auto load_chunk = [&](int c) {
        __nv_bfloat16* base = sg + (c % NSTG) * GSTAGE;
        const int k0 = c * 64;
#pragma unroll 4
        for (int i = tid; i < 1024; i += 256) {
            const int r  = i >> 3;
            const int ck = (i & 7) * 8;
            const int so = r * GST + ck;
            cpa16(base + 0 * GTILE + so, Ah + (size_t)(m0 + r) * DD + k0 + ck);
            cpa16(base + 1 * GTILE + so, Al + (size_t)(m0 + r) * DD + k0 + ck);
            cpa16(base + 2 * GTILE + so, Wh + (size_t)(n0 + r) * DD + k0 + ck);
            cpa16(base + 3 * GTILE + so, Wl + (size_t)(n0 + r) * DD + k0 + ck);
        }
        cpa_commit();
    };

    float acc[4][4][4];
#pragma unroll
    for (int i = 0; i < 4; i++)
#pragma unroll
        for (int j = 0; j < 4; j++)
#pragma unroll
            for (int c = 0; c < 4; c++) acc[i][j][c] = 0.0f;

    load_chunk(0);
    load_chunk(1);

    for (int ch = 0; ch < NCH; ch++) {
        if (ch + 1 < NCH) cpa_wait1();   // chunk ch resident (ch+1 may pend)
        else              cpa_wait0();
        __syncthreads();                 // everyone sees chunk ch; prev compute done
        if (ch + 2 < NCH) load_chunk(ch + 2);

        const __nv_bfloat16* cur = sg + (ch % NSTG) * GSTAGE;
        const __nv_bfloat16* Ahi = cur;
        const __nv_bfloat16* Alo = cur + GTILE;
        const __nv_bfloat16* Bhi = cur + 2 * GTILE;
        const __nv_bfloat16* Blo = cur + 3 * GTILE;

#pragma unroll
        for (int kk = 0; kk < 4; kk++) {
            uint32_t ahi[4][4], alo[4][4], bhi[2][4], blo[2][4];
            const int ar = wm * 64 + (lane & 15);
            const int ak = kk * 16 + (lane >> 4) * 8;
#pragma unroll
            for (int mi = 0; mi < 4; mi++) {
                ldmat_x4(ahi[mi], saddr(Ahi + (ar + mi * 16) * GST + ak));
                ldmat_x4(alo[mi], saddr(Alo + (ar + mi * 16) * GST + ak));
            }
            const int br = wn * 32 + ((lane >> 4) & 1) * 8 + (lane & 7);
            const int bk = kk * 16 + ((lane >> 3) & 1) * 8;
#pragma unroll
            for (int p = 0; p < 2; p++) {
                ldmat_x4(bhi[p], saddr(Bhi + (br + p * 16) * GST + bk));
                ldmat_x4(blo[p], saddr(Blo + (br + p * 16) * GST + bk));
            }
#pragma unroll
            for (int mi = 0; mi < 4; mi++)
#pragma unroll
                for (int ni = 0; ni < 4; ni++) {
                    const uint32_t* bh = &bhi[ni >> 1][(ni & 1) * 2];
                    const uint32_t* bl = &blo[ni >> 1][(ni & 1) * 2];
                    mma16816(acc[mi][ni], ahi[mi], bh[0], bh[1]);
                    mma16816(acc[mi][ni], ahi[mi], bl[0], bl[1]);
                    mma16816(acc[mi][ni], alo[mi], bh[0], bh[1]);
                }
        }
    }

#pragma unroll
    for (int mi = 0; mi < 4; mi++)
#pragma unroll
        for (int ni = 0; ni < 4; ni++) {
            const int r0 = m0 + wm * 64 + mi * 16 + (lane >> 2);
            const int c0 = n0 + wn * 32 + ni * 8 + (lane & 3) * 2;
            *(float2*)(C + (size_t)r0 * 1024 + c0) =
                make_float2(acc[mi][ni][0], acc[mi][ni][1]);
            *(float2*)(C + (size_t)(r0 + 8) * 1024 + c0) =
                make_float2(acc[mi][ni][2], acc[mi][ni][3]);
        }
}

// ---------------------------------------------------------------------------
// RoPE + split to bf16 hi/lo
// ---------------------------------------------------------------------------
__global__ void rope_split(const float* __restrict__ p5,
                           __nv_bfloat16* __restrict__ qh,  __nv_bfloat16* __restrict__ ql,
                           __nv_bfloat16* __restrict__ kh,  __nv_bfloat16* __restrict__ kl,
                           __nv_bfloat16* __restrict__ q2h, __nv_bfloat16* __restrict__ q2l,
                           __nv_bfloat16* __restrict__ k2h, __nv_bfloat16* __restrict__ k2l,
                           __nv_bfloat16* __restrict__ vh,  __nv_bfloat16* __restrict__ vl) {
    const int idx = blockIdx.x * blockDim.x + threadIdx.x;
    const int i = idx & 31;
    const int h = (idx >> 5) & (HH - 1);
    const int t = (idx >> 9) & (TT - 1);
    const int b = idx >> 20;

    const float inv_freq = powf(10000.0f, -(float)i * (1.0f / 32.0f));
    float c, s;
    sincosf((float)t * inv_freq, &s, &c);

    const size_t base = ((size_t)(b * TT + t)) * DD + h * DH + i;

    __nv_bfloat16* oh[4] = {qh, kh, q2h, k2h};
    __nv_bfloat16* ol[4] = {ql, kl, q2l, k2l};
#pragma unroll
    for (int a = 0; a < 4; a++) {
        const float* in = p5 + (size_t)a * MM * DD;
        float x1 = in[base];
        float x2 = in[base + 32];
        float y1 = fmaf(x1, c, x2 * s);
        float y2 = fmaf(-x1, s, x2 * c);
        unsigned short hh, lll;
        fsplit(y1, hh, lll);
        oh[a][base]      = __ushort_as_bfloat16(hh);
        ol[a][base]      = __ushort_as_bfloat16(lll);
        fsplit(y2, hh, lll);
        oh[a][base + 32] = __ushort_as_bfloat16(hh);
        ol[a][base + 32] = __ushort_as_bfloat16(lll);
    }
    {
        const float* vv = p5 + (size_t)4 * MM * DD;
        unsigned short hh, lll;
        fsplit(vv[base], hh, lll);
        vh[base]      = __ushort_as_bfloat16(hh);
        vl[base]      = __ushort_as_bfloat16(lll);
        fsplit(vv[base + 32], hh, lll);
        vh[base + 32] = __ushort_as_bfloat16(hh);
        vl[base + 32] = __ushort_as_bfloat16(lll);
    }
}

// ---------------------------------------------------------------------------
// Tensor-core causal bilinear attention; epilogue writes z as bf16 hi/lo.
// ---------------------------------------------------------------------------
__global__ void __launch_bounds__(256, 1) attn_mma(
        const __nv_bfloat16* __restrict__ qh,  const __nv_bfloat16* __restrict__ ql,
        const __nv_bfloat16* __restrict__ q2h, const __nv_bfloat16* __restrict__ q2l,
        const __nv_bfloat16* __restrict__ kh,  const __nv_bfloat16* __restrict__ kl,
        const __nv_bfloat16* __restrict__ k2h, const __nv_bfloat16* __restrict__ k2l,
        const __nv_bfloat16* __restrict__ vh,  const __nv_bfloat16* __restrict__ vl,
        __nv_bfloat16* __restrict__ zh, __nv_bfloat16* __restrict__ zl) {
    extern __shared__ __nv_bfloat16 sb2[];
    const int tid  = threadIdx.x;
    const int lane = tid & 31;
    const int w    = tid >> 5;
    const int qb = (int)gridDim.x - 1 - (int)blockIdx.x;
    const int q0 = qb * 128;
    const int b  = blockIdx.y >> 4;
    const int h  = blockIdx.y & 15;
    const size_t bh_off = (size_t)b * TT * DD + h * DH;

    {
        const __nv_bfloat16* src[4] = {qh, ql, q2h, q2l};
#pragma unroll
        for (int a = 0; a < 4; a++) {
            __nv_bfloat16* dst = sb2 + a * 128 * KST;
            for (int i = tid; i < 1024; i += 256) {
                const int r = i >> 3, ck = (i & 7) * 8;
                cpa16(dst + r * KST + ck, src[a] + bh_off + (size_t)(q0 + r) * DD + ck);
            }
        }
        cpa_commit();
        cpa_wait0();
        __syncthreads();
    }

    uint32_t fqh[4][4], fql[4][4], fq2h[4][4], fq2l[4][4];
    {
        const int ar = w * 16 + (lane & 15);
        const int ak = (lane >> 4) * 8;
#pragma unroll
        for (int kf = 0; kf < 4; kf++) {
            ldmat_x4(fqh [kf], saddr(sb2 + 0 * 128 * KST + ar * KST + kf * 16 + ak));
            ldmat_x4(fql [kf], saddr(sb2 + 1 * 128 * KST + ar * KST + kf * 16 + ak));
            ldmat_x4(fq2h[kf], saddr(sb2 + 2 * 128 * KST + ar * KST + kf * 16 + ak));
            ldmat_x4(fq2l[kf], saddr(sb2 + 3 * 128 * KST + ar * KST + kf * 16 + ak));
        }
    }
    __syncthreads();

    float zacc[8][4];
#pragma unroll
    for (int i = 0; i < 8; i++)
#pragma unroll
        for (int j = 0; j < 4; j++) zacc[i][j] = 0.0f;

    const int nkv = 2 * qb + 2;
    const int br = (lane & 7) + ((lane >> 4) & 1) * 8;
    const int bk = ((lane >> 3) & 1) * 8;
    const float invd2 = 1.0f / ((float)DH * (float)DH);

    auto load_tile = [&](int kj, int buf) {
        __nv_bfloat16* base = sb2 + buf * STAGE;
        const int kv0 = kj * 64;
        const __nv_bfloat16* src[4] = {kh, kl, k2h, k2l};
#pragma unroll
        for (int a = 0; a < 4; a++) {
            __nv_bfloat16* dst = base + a * ATILE;
            for (int i = tid; i < 512; i += 256) {
                const int r = i >> 3, ck = (i & 7) * 8;
                cpa16(dst + r * KST + ck, src[a] + bh_off + (size_t)(kv0 + r) * DD + ck);
            }
        }
        {
            const int r  = tid & 63;
            const int dg = (tid >> 6) * 16;
            const __nv_bfloat16* s1p = vh + bh_off + (size_t)(kv0 + r) * DD + dg;
            const __nv_bfloat16* s2p = vl + bh_off + (size_t)(kv0 + r) * DD + dg;
            unsigned short t1[16], t2[16];
            *(uint4*)t1       = *(const uint4*)s1p;
            *(uint4*)(t1 + 8) = *(const uint4*)(s1p + 8);
            *(uint4*)t2       = *(const uint4*)s2p;
            *(uint4*)(t2 + 8) = *(const uint4*)(s2p + 8);
            unsigned short* dh = (unsigned short*)(base + 4 * ATILE);
            unsigned short* dl = (unsigned short*)(base + 5 * ATILE);
#pragma unroll
            for (int j = 0; j < 16; j++) {
                dh[(dg + j) * KST + r] = t1[j];
                dl[(dg + j) * KST + r] = t2[j];
            }
        }
    };

    load_tile(0, 0);
    cpa_commit();

    for (int kj = 0; kj < nkv; kj++) {
        cpa_wait0();
        __syncthreads();   // tile kj visible to all; prev compute done
        if (kj + 1 < nkv) {
            load_tile(kj + 1, (kj + 1) & 1);
            cpa_commit();
        }

        const __nv_bfloat16* base = sb2 + (kj & 1) * STAGE;
        const int kv0 = kj * 64;
        const bool masked = (kv0 >= q0);

        uint32_t ph[8][2], pl[8][2];
#pragma unroll
        for (int g = 0; g < 4; g++) {
            float s1f[2][4], s2f[2][4];
#pragma unroll
            for (int p = 0; p < 2; p++)
#pragma unroll
                for (int e = 0; e < 4; e++) { s1f[p][e] = 0.0f; s2f[p][e] = 0.0f; }

#pragma unroll
            for (int kf = 0; kf < 4; kf++) {
                uint32_t bh_[4], bl_[4];
                const int off = (g * 16 + br) * KST + kf * 16 + bk;
                ldmat_x4(bh_, saddr(base + 0 * ATILE + off));
                ldmat_x4(bl_, saddr(base + 1 * ATILE + off));
#pragma unroll
                for (int p = 0; p < 2; p++) {
                    mma16816(s1f[p], fqh[kf], bh_[p*2], bh_[p*2+1]);
                    mma16816(s1f[p], fqh[kf], bl_[p*2], bl_[p*2+1]);
                    mma16816(s1f[p], fql[kf], bh_[p*2], bh_[p*2+1]);
                }
                ldmat_x4(bh_, saddr(base + 2 * ATILE + off));
                ldmat_x4(bl_, saddr(base + 3 * ATILE + off));
#pragma unroll
                for (int p = 0; p < 2; p++) {
                    mma16816(s2f[p], fq2h[kf], bh_[p*2], bh_[p*2+1]);
                    mma16816(s2f[p], fq2h[kf], bl_[p*2], bl_[p*2+1]);
                    mma16816(s2f[p], fq2l[kf], bh_[p*2], bh_[p*2+1]);
                }
            }
#pragma unroll
            for (int p = 0; p < 2; p++) {
                const int j = g * 2 + p;
                float pr[4];
#pragma unroll
                for (int e = 0; e < 4; e++) pr[e] = s1f[p][e] * s2f[p][e] * invd2;
                if (masked) {
                    const int qr = q0 + w * 16 + (lane >> 2);
                    const int kc = kv0 + j * 8 + (lane & 3) * 2;
                    if (kc     > qr)     pr[0] = 0.0f;
                    if (kc + 1 > qr)     pr[1] = 0.0f;
                    if (kc     > qr + 8) pr[2] = 0.0f;
                    if (kc + 1 > qr + 8) pr[3] = 0.0f;
                }
                unsigned short hh[4], ll[4];
#pragma unroll
                for (int e = 0; e < 4; e++) fsplit(pr[e], hh[e], ll[e]);
                ph[j][0] = (uint32_t)hh[1] << 16 | hh[0];
                ph[j][1] = (uint32_t)hh[3] << 16 | hh[2];
                pl[j][0] = (uint32_t)ll[1] << 16 | ll[0];
                pl[j][1] = (uint32_t)ll[3] << 16 | ll[2];
            }
        }

#pragma unroll
        for (int f = 0; f < 4; f++) {
            uint32_t ah[4] = {ph[2*f][0], ph[2*f][1], ph[2*f+1][0], ph[2*f+1][1]};
            uint32_t al[4] = {pl[2*f][0], pl[2*f][1], pl[2*f+1][0], pl[2*f+1][1]};
#pragma unroll
            for (int gd = 0; gd < 4; gd++) {
                uint32_t vh_[4], vl_[4];
                const int off = (gd * 16 + br) * KST + f * 16 + bk;
                ldmat_x4(vh_, saddr(base + 4 * ATILE + off));
                ldmat_x4(vl_, saddr(base + 5 * ATILE + off));
#pragma unroll
                for (int p = 0; p < 2; p++) {
                    mma16816(zacc[gd*2+p], ah, vh_[p*2], vh_[p*2+1]);
                    mma16816(zacc[gd*2+p], ah, vl_[p*2], vl_[p*2+1]);
                    mma16816(zacc[gd*2+p], al, vh_[p*2], vh_[p*2+1]);
                }
            }
        }
    }

    // epilogue: split z to bf16 hi/lo and store directly
    {
        const int r = q0 + w * 16 + (lane >> 2);
        const int c = (lane & 3) * 2;
#pragma unroll
        for (int nd = 0; nd < 8; nd++) {
            unsigned short h0, l0, h1, l1;
#pragma unroll
            for (int half = 0; half < 2; half++) {
                fsplit(zacc[nd][half * 2 + 0], h0, l0);
                fsplit(zacc[nd][half * 2 + 1], h1, l1);
                const size_t off = bh_off + (size_t)(r + half * 8) * DD + nd * 8 + c;
                *(uint32_t*)(zh + off) = (uint32_t)h1 << 16 | h0;
                *(uint32_t*)(zl + off) = (uint32_t)l1 << 16 | l0;
            }
        }
    }
}

// ---------------------------------------------------------------------------
extern "C" void kernel_launch(void* const* d_in, const int* in_sizes, int n_in,
                              void* d_out, int out_size) {
    const float* x     = (const float*)d_in[0];
    const float* Wq    = (const float*)d_in[1];
    const float* Wk    = (const float*)d_in[2];
    const float* Wq2   = (const float*)d_in[3];
    const float* Wk2   = (const float*)d_in[4];
    const float* Wv    = (const float*)d_in[5];
    const float* Wproj = (const float*)d_in[6];
    float* out = (float*)d_out;

    float* p5;
    cudaGetSymbolAddress((void**)&p5, g_p5);

    __nv_bfloat16 *xh, *xl, *zh, *zl, *w6h, *w6l;
    cudaGetSymbolAddress((void**)&xh,  g_xh);  cudaGetSymbolAddress((void**)&xl,  g_xl);
    cudaGetSymbolAddress((void**)&zh,  g_zh);  cudaGetSymbolAddress((void**)&zl,  g_zl);
    cudaGetSymbolAddress((void**)&w6h, g_w6h); cudaGetSymbolAddress((void**)&w6l, g_w6l);

    __nv_bfloat16 *qh, *ql, *q2h, *q2l, *kh, *kl, *k2h, *k2l, *vh, *vl;
    cudaGetSymbolAddress((void**)&qh,  g_qh);  cudaGetSymbolAddress((void**)&ql,  g_ql);
    cudaGetSymbolAddress((void**)&q2h, g_q2h); cudaGetSymbolAddress((void**)&q2l, g_q2l);
    cudaGetSymbolAddress((void**)&kh,  g_kh);  cudaGetSymbolAddress((void**)&kl,  g_kl);
    cudaGetSymbolAddress((void**)&k2h, g_k2h); cudaGetSymbolAddress((void**)&k2l, g_k2l);
    cudaGetSymbolAddress((void**)&vh,  g_vh);  cudaGetSymbolAddress((void**)&vl,  g_vl);

    cudaFuncSetAttribute(gemm_bf16,
                         cudaFuncAttributeMaxDynamicSharedMemorySize, GEMM_SMEM);

    // 1) split inputs
    split_f32<<<MM * DD / 1024, 256>>>(x, xh, xl);
    split_w6<<<dim3(DD * DD / 1024, 6), 256>>>(Wq, Wk, Wq2, Wk2, Wv, Wproj, w6h, w6l);

    // 2) five fused projections
    gemm_bf16<<<dim3(DD / 128, MM / 128, 5), 256, GEMM_SMEM>>>(xh, xl, w6h, w6l, p5);

    // 3) rope + split
    rope_split<<<(BB * TT * HH * 32) / 256, 256>>>(p5, qh, ql, kh, kl,
                                                   q2h, q2l, k2h, k2l, vh, vl);

    // 4) attention (writes zh/zl directly)
    const int attn_smem = 2 * STAGE * (int)sizeof(__nv_bfloat16);
    cudaFuncSetAttribute(attn_mma,
                         cudaFuncAttributeMaxDynamicSharedMemorySize, attn_smem);
    attn_mma<<<dim3(TT / 128, BB * HH), 256, attn_smem>>>(
        qh, ql, q2h, q2l, kh, kl, k2h, k2l, vh, vl, zh, zl);

    // 5) output projection
    gemm_bf16<<<dim3(DD / 128, MM / 128, 1), 256, GEMM_SMEM>>>(
        zh, zl, w6h + (size_t)5 * DD * DD, w6l + (size_t)5 * DD * DD, out);
}